// round 1
// baseline (speedup 1.0000x reference)
#include <cuda_runtime.h>
#include <math.h>

#define Bn 256
#define Tn 100
#define Fn 256
#define Hn 512
#define NB 128
#define NT 256

// ---------------- scratch (device globals: allocation-free rule) ----------------
__device__ float g_gamma_h[(size_t)Bn * Tn * Hn];   // [(b*T+t)*H + j]
__device__ float g_alpha[(size_t)Bn * Tn * Fn];     // [(b*T+t)*F + f]
__device__ float g_xh[Bn * Fn];
__device__ float g_cc[Bn * Fn];
__device__ float g_hdec[2][Bn * Hn];                // double-buffered (parity t&1)
__device__ float g_c[Bn * Hn];
__device__ float g_l1[Tn * 64];
__device__ float g_l2[Tn * 64];
__device__ float g_l3[Tn * 64];
__device__ float g_den[Tn * 64];
__device__ unsigned g_bar_count = 0;
__device__ unsigned g_bar_sense = 0;

__device__ __forceinline__ float sigmoidf_(float x) { return 1.0f / (1.0f + expf(-x)); }

// Sense-reversing grid barrier. Valid because grid (128) <= SM count (152),
// 1 CTA/SM => all CTAs co-resident in wave 1.
__device__ __forceinline__ void gsync(unsigned& sense) {
    __syncthreads();
    __threadfence();
    unsigned target = sense ^ 1u;
    if (threadIdx.x == 0) {
        unsigned old = atomicAdd(&g_bar_count, 1u);
        if (old == NB - 1) {
            g_bar_count = 0;               // reset; nobody touches count until sense flips
            __threadfence();
            atomicExch(&g_bar_sense, target);
        } else {
            while (atomicAdd(&g_bar_sense, 0u) != target) { __nanosleep(128); }
        }
        __threadfence();
    }
    sense = target;
    __syncthreads();
}

// deterministic CTA reduction, result -> *dst
__device__ __forceinline__ void cta_reduce_store(float* SM, float v, float* dst) {
    __syncthreads();
    SM[threadIdx.x] = v;
    __syncthreads();
#pragma unroll
    for (int s = 128; s > 0; s >>= 1) {
        if (threadIdx.x < s) SM[threadIdx.x] += SM[threadIdx.x + s];
        __syncthreads();
    }
    if (threadIdx.x == 0) *dst = SM[0];
    __syncthreads();
}

__global__ void __launch_bounds__(NT) rits_kernel(
    const float* __restrict__ values, const float* __restrict__ masks,
    const float* __restrict__ deltas,
    const float* __restrict__ W_td_h, const float* __restrict__ b_td_h,
    const float* __restrict__ W_td_x, const float* __restrict__ b_td_x,
    const float* __restrict__ W_hist, const float* __restrict__ b_hist,
    const float* __restrict__ W_feat, const float* __restrict__ b_feat,
    const float* __restrict__ W_comb, const float* __restrict__ b_comb,
    const float* __restrict__ W_ih, const float* __restrict__ W_hh,
    const float* __restrict__ b_ih, const float* __restrict__ b_hh,
    float* __restrict__ out)
{
    __shared__ float SM[4224];
    float* As = SM;            // 2112 floats
    float* Ws = SM + 2112;     // 2112 floats

    const int tid = threadIdx.x;
    const int cta = blockIdx.x;

    unsigned sense = *((volatile unsigned*)&g_bar_sense);  // stable at entry

    // ---------- init state ----------
    for (int i = cta * NT + tid; i < Bn * Hn; i += NB * NT) {
        g_c[i] = 0.0f;
        g_hdec[0][i] = 0.0f;
        g_hdec[1][i] = 0.0f;
    }

    // ---------- precompute gamma_h_all and alpha_all (input-only, hoisted out of the loop) ----------
    // gamma tiles: 400 x 8 = 3200 (M=B*T, N=H, K=F);  alpha tiles: 400 x 4 = 1600 (N=F, K=2F)
    {
        const int tx = tid & 15, ty = tid >> 4;
        for (int tile = cta; tile < 4800; tile += NB) {
            float acc[4][4];
#pragma unroll
            for (int i = 0; i < 4; i++)
#pragma unroll
                for (int j = 0; j < 4; j++) acc[i][j] = 0.0f;

            if (tile < 3200) {
                // gamma_h: exp(-relu(D @ W_td_h^T + b_td_h)),  D rows = bt = b*T+t
                const int m0 = (tile >> 3) * 64;
                const int n0 = (tile & 7) * 64;
                for (int k0 = 0; k0 < Fn; k0 += 32) {
#pragma unroll
                    for (int q = 0; q < 8; q++) {
                        int idx = tid + q * 256;
                        int r = idx >> 5, kk = idx & 31;
                        As[r * 33 + kk] = deltas[(size_t)(m0 + r) * Fn + k0 + kk];
                        Ws[r * 33 + kk] = W_td_h[(size_t)(n0 + r) * Fn + k0 + kk];
                    }
                    __syncthreads();
#pragma unroll
                    for (int kk = 0; kk < 32; kk++) {
                        float a[4], w[4];
#pragma unroll
                        for (int i = 0; i < 4; i++) a[i] = As[(ty * 4 + i) * 33 + kk];
#pragma unroll
                        for (int j = 0; j < 4; j++) w[j] = Ws[(tx * 4 + j) * 33 + kk];
#pragma unroll
                        for (int i = 0; i < 4; i++)
#pragma unroll
                            for (int j = 0; j < 4; j++) acc[i][j] += a[i] * w[j];
                    }
                    __syncthreads();
                }
#pragma unroll
                for (int i = 0; i < 4; i++) {
#pragma unroll
                    for (int j = 0; j < 4; j++) {
                        int bt = m0 + ty * 4 + i;
                        int n = n0 + tx * 4 + j;
                        g_gamma_h[(size_t)bt * Hn + n] =
                            expf(-fmaxf(acc[i][j] + b_td_h[n], 0.0f));
                    }
                }
            } else {
                // alpha: sigmoid([gamma_x, m] @ W_comb^T + b_comb)
                const int t2 = tile - 3200;
                const int m0 = (t2 >> 2) * 64;
                const int n0 = (t2 & 3) * 64;
                for (int k0 = 0; k0 < 2 * Fn; k0 += 32) {
#pragma unroll
                    for (int q = 0; q < 8; q++) {
                        int idx = tid + q * 256;
                        int r = idx >> 5, kk = idx & 31;
                        int kg = k0 + kk;
                        int bt = m0 + r;
                        float v;
                        if (kg < Fn) {
                            float d = deltas[(size_t)bt * Fn + kg];
                            v = expf(-fmaxf(d * W_td_x[kg * Fn + kg] + b_td_x[kg], 0.0f));
                        } else {
                            v = masks[(size_t)bt * Fn + (kg - Fn)];
                        }
                        As[r * 33 + kk] = v;
                        Ws[r * 33 + kk] = W_comb[(size_t)(n0 + r) * (2 * Fn) + kg];
                    }
                    __syncthreads();
#pragma unroll
                    for (int kk = 0; kk < 32; kk++) {
                        float a[4], w[4];
#pragma unroll
                        for (int i = 0; i < 4; i++) a[i] = As[(ty * 4 + i) * 33 + kk];
#pragma unroll
                        for (int j = 0; j < 4; j++) w[j] = Ws[(tx * 4 + j) * 33 + kk];
#pragma unroll
                        for (int i = 0; i < 4; i++)
#pragma unroll
                            for (int j = 0; j < 4; j++) acc[i][j] += a[i] * w[j];
                    }
                    __syncthreads();
                }
#pragma unroll
                for (int i = 0; i < 4; i++) {
#pragma unroll
                    for (int j = 0; j < 4; j++) {
                        int bt = m0 + ty * 4 + i;
                        int n = n0 + tx * 4 + j;
                        g_alpha[(size_t)bt * Fn + n] = sigmoidf_(acc[i][j] + b_comb[n]);
                    }
                }
            }
        }
    }

    gsync(sense);

    // ---------- sequential recurrence ----------
    for (int t = 0; t < Tn; t++) {
        const float* hdec_r = g_hdec[t & 1];
        float* hdec_w = g_hdec[(t + 1) & 1];

        // ===== P_a: x_h = h_dec @ W_hist^T + b_hist   (M=256,N=256,K=512) =====
        if (cta < 64) {
            const int m0 = (cta >> 3) * 32;
            const int n0 = (cta & 7) * 32;
            const int tx = tid & 15, ty = tid >> 4;
            float acc[2][2] = {{0.f, 0.f}, {0.f, 0.f}};
            for (int k0 = 0; k0 < Hn; k0 += 32) {
#pragma unroll
                for (int q = 0; q < 4; q++) {
                    int idx = tid + q * 256;
                    int r = idx >> 5, kk = idx & 31;
                    As[r * 33 + kk] = hdec_r[(m0 + r) * Hn + k0 + kk];
                    Ws[r * 33 + kk] = W_hist[(size_t)(n0 + r) * Hn + k0 + kk];
                }
                __syncthreads();
#pragma unroll
                for (int kk = 0; kk < 32; kk++) {
                    float a0 = As[(ty * 2 + 0) * 33 + kk];
                    float a1 = As[(ty * 2 + 1) * 33 + kk];
                    float w0 = Ws[(tx * 2 + 0) * 33 + kk];
                    float w1 = Ws[(tx * 2 + 1) * 33 + kk];
                    acc[0][0] += a0 * w0; acc[0][1] += a0 * w1;
                    acc[1][0] += a1 * w0; acc[1][1] += a1 * w1;
                }
                __syncthreads();
            }
            float ls = 0.0f;
#pragma unroll
            for (int i = 0; i < 2; i++) {
#pragma unroll
                for (int j = 0; j < 2; j++) {
                    int b = m0 + ty * 2 + i;
                    int f = n0 + tx * 2 + j;
                    float xh = acc[i][j] + b_hist[f];
                    g_xh[b * Fn + f] = xh;
                    size_t vi = (size_t)(b * Tn + t) * Fn + f;
                    float x = values[vi], m = masks[vi];
                    ls += fabsf(xh - x) * m;
                }
            }
            cta_reduce_store(SM, ls, &g_l1[t * 64 + cta]);
        }
        gsync(sense);

        // ===== P_b: z_h = relu(x_c @ Wf_masked^T + b_feat); fused c_h/c_c/imputed/losses =====
        if (cta < 64) {
            const int m0 = (cta >> 3) * 32;
            const int n0 = (cta & 7) * 32;
            const int tx = tid & 15, ty = tid >> 4;
            float acc[2][2] = {{0.f, 0.f}, {0.f, 0.f}};
            for (int k0 = 0; k0 < Fn; k0 += 32) {
#pragma unroll
                for (int q = 0; q < 4; q++) {
                    int idx = tid + q * 256;
                    int r = idx >> 5, kk = idx & 31;
                    int kg = k0 + kk;
                    int b = m0 + r;
                    size_t vi = (size_t)(b * Tn + t) * Fn + kg;
                    float m = masks[vi], x = values[vi];
                    As[r * 33 + kk] = m * x + (1.0f - m) * g_xh[b * Fn + kg];
                    int n = n0 + r;
                    Ws[r * 33 + kk] = (n == kg) ? 0.0f : W_feat[(size_t)n * Fn + kg];
                }
                __syncthreads();
#pragma unroll
                for (int kk = 0; kk < 32; kk++) {
                    float a0 = As[(ty * 2 + 0) * 33 + kk];
                    float a1 = As[(ty * 2 + 1) * 33 + kk];
                    float w0 = Ws[(tx * 2 + 0) * 33 + kk];
                    float w1 = Ws[(tx * 2 + 1) * 33 + kk];
                    acc[0][0] += a0 * w0; acc[0][1] += a0 * w1;
                    acc[1][0] += a1 * w0; acc[1][1] += a1 * w1;
                }
                __syncthreads();
            }
            float l2s = 0.0f, l3s = 0.0f, dns = 0.0f;
#pragma unroll
            for (int i = 0; i < 2; i++) {
#pragma unroll
                for (int j = 0; j < 2; j++) {
                    int b = m0 + ty * 2 + i;
                    int f = n0 + tx * 2 + j;
                    size_t bt = (size_t)(b * Tn + t);
                    float z = fmaxf(acc[i][j] + b_feat[f], 0.0f);
                    float al = g_alpha[bt * Fn + f];
                    float xh = g_xh[b * Fn + f];
                    float ch = al * z + (1.0f - al) * xh;
                    size_t vi = bt * Fn + f;
                    float x = values[vi], m = masks[vi];
                    float cc = m * x + (1.0f - m) * ch;
                    out[vi] = cc;                 // imputed == c_c
                    g_cc[b * Fn + f] = cc;
                    l2s += fabsf(z - x) * m;
                    l3s += fabsf(ch - x) * m;
                    dns += m;
                }
            }
            cta_reduce_store(SM, l2s, &g_l2[t * 64 + cta]);
            cta_reduce_store(SM, l3s, &g_l3[t * 64 + cta]);
            cta_reduce_store(SM, dns, &g_den[t * 64 + cta]);
        }
        gsync(sense);

        // ===== P_c: gates GEMM (M=256, N=512 cols x 4 gates, K=1024) + fused LSTM =====
        {
            const int m0 = (cta >> 5) * 64;   // 4 M-tiles
            const int n0 = (cta & 31) * 16;   // 32 N-tiles (H columns)
            const int c = tid & 15;
            const int rg = tid >> 4;          // 0..15
            float acc[4][4];                  // [row_i][gate]
#pragma unroll
            for (int i = 0; i < 4; i++)
#pragma unroll
                for (int g = 0; g < 4; g++) acc[i][g] = 0.0f;

            for (int k0 = 0; k0 < 1024; k0 += 32) {
#pragma unroll
                for (int q = 0; q < 8; q++) {
                    int idx = tid + q * 256;
                    int r = idx >> 5, kk = idx & 31;
                    int b = m0 + r;
                    int kg = k0 + kk;
                    float v;
                    if (kg < 256)      v = g_cc[b * Fn + kg];
                    else if (kg < 512) v = masks[(size_t)(b * Tn + t) * Fn + (kg - 256)];
                    else               v = hdec_r[b * Hn + (kg - 512)];
                    As[r * 33 + kk] = v;
                }
#pragma unroll
                for (int q = 0; q < 8; q++) {
                    int idx = tid + q * 256;
                    int wr = idx >> 5, kk = idx & 31;
                    int g = wr >> 4, c2 = wr & 15;
                    int row = g * Hn + n0 + c2;
                    int kg = k0 + kk;
                    Ws[wr * 33 + kk] = (kg < 512)
                        ? W_ih[(size_t)row * 512 + kg]
                        : W_hh[(size_t)row * 512 + (kg - 512)];
                }
                __syncthreads();
#pragma unroll
                for (int kk = 0; kk < 32; kk++) {
                    float a0 = As[(rg * 4 + 0) * 33 + kk];
                    float a1 = As[(rg * 4 + 1) * 33 + kk];
                    float a2 = As[(rg * 4 + 2) * 33 + kk];
                    float a3 = As[(rg * 4 + 3) * 33 + kk];
                    float w0 = Ws[(0 * 16 + c) * 33 + kk];
                    float w1 = Ws[(1 * 16 + c) * 33 + kk];
                    float w2 = Ws[(2 * 16 + c) * 33 + kk];
                    float w3 = Ws[(3 * 16 + c) * 33 + kk];
                    acc[0][0] += a0 * w0; acc[0][1] += a0 * w1; acc[0][2] += a0 * w2; acc[0][3] += a0 * w3;
                    acc[1][0] += a1 * w0; acc[1][1] += a1 * w1; acc[1][2] += a1 * w2; acc[1][3] += a1 * w3;
                    acc[2][0] += a2 * w0; acc[2][1] += a2 * w1; acc[2][2] += a2 * w2; acc[2][3] += a2 * w3;
                    acc[3][0] += a3 * w0; acc[3][1] += a3 * w1; acc[3][2] += a3 * w2; acc[3][3] += a3 * w3;
                }
                __syncthreads();
            }
            const int j = n0 + c;
            const float bi0 = b_ih[0 * Hn + j] + b_hh[0 * Hn + j];
            const float bi1 = b_ih[1 * Hn + j] + b_hh[1 * Hn + j];
            const float bi2 = b_ih[2 * Hn + j] + b_hh[2 * Hn + j];
            const float bi3 = b_ih[3 * Hn + j] + b_hh[3 * Hn + j];
#pragma unroll
            for (int i = 0; i < 4; i++) {
                int b = m0 + rg * 4 + i;
                float ig = sigmoidf_(acc[i][0] + bi0);
                float fg = sigmoidf_(acc[i][1] + bi1);
                float gg = tanhf(acc[i][2] + bi2);
                float og = sigmoidf_(acc[i][3] + bi3);
                int ci = b * Hn + j;
                float cn = fg * g_c[ci] + ig * gg;
                float hn = og * tanhf(cn);
                g_c[ci] = cn;
                if (t + 1 < Tn) {
                    hdec_w[ci] = hn * g_gamma_h[(size_t)(b * Tn + t + 1) * Hn + j];
                } else {
                    out[(size_t)Bn * Tn * Fn + ci] = hn;   // final h
                }
            }
        }
        gsync(sense);
    }

    // ---------- final deterministic loss reduction ----------
    if (cta == 0) {
        float v = 0.0f;
        if (tid < Tn) {
            float den = 1e-9f, n1 = 0.f, n2 = 0.f, n3 = 0.f;
            for (int c2 = 0; c2 < 64; c2++) {
                den += g_den[tid * 64 + c2];
                n1 += g_l1[tid * 64 + c2];
                n2 += g_l2[tid * 64 + c2];
                n3 += g_l3[tid * 64 + c2];
            }
            v = (n1 + n2 + n3) / den;
        }
        __syncthreads();
        SM[tid] = v;
        __syncthreads();
#pragma unroll
        for (int s = 128; s > 0; s >>= 1) {
            if (tid < s) SM[tid] += SM[tid + s];
            __syncthreads();
        }
        if (tid == 0) out[(size_t)Bn * Tn * Fn + Bn * Hn] = SM[0] / (3.0f * Tn);
    }
}

extern "C" void kernel_launch(void* const* d_in, const int* in_sizes, int n_in,
                              void* d_out, int out_size) {
    (void)in_sizes; (void)n_in; (void)out_size;
    rits_kernel<<<NB, NT>>>(
        (const float*)d_in[0],  (const float*)d_in[1],  (const float*)d_in[2],
        (const float*)d_in[3],  (const float*)d_in[4],  (const float*)d_in[5],
        (const float*)d_in[6],  (const float*)d_in[7],  (const float*)d_in[8],
        (const float*)d_in[9],  (const float*)d_in[10], (const float*)d_in[11],
        (const float*)d_in[12], (const float*)d_in[13], (const float*)d_in[14],
        (const float*)d_in[15], (const float*)d_in[16],
        (float*)d_out);
}

// round 2
// speedup vs baseline: 2.1930x; 2.1930x over previous
#include <cuda_runtime.h>
#include <math.h>

#define Bn 256
#define Tn 100
#define Fn 256
#define Hn 512
#define NB 128
#define NT 256
#define NGRP 4
#define GSZ 32      // CTAs per group
#define GROWS 64    // batch rows per group
#define PIT 36      // smem staging pitch (floats)
#define APIT 80     // epilogue accum pitch

// ---------------- scratch (device globals: allocation-free rule) ----------------
__device__ float g_gamma_h[(size_t)Bn * Tn * Hn];
__device__ float g_alpha[(size_t)Bn * Tn * Fn];
__device__ float g_gx[(size_t)Bn * Tn * Fn];
__device__ float g_xh[Bn * Fn];
__device__ float g_cc[Bn * Fn];
__device__ float g_hdec[2][Bn * Hn];
__device__ float g_c[Bn * Hn];
__device__ float g_l1[Tn * 64], g_l2[Tn * 64], g_l3[Tn * 64], g_den[Tn * 64];
__device__ unsigned g_cnt_all, g_sense_all;
__device__ unsigned g_cnt_grp[NGRP], g_sense_grp[NGRP];

__device__ __forceinline__ float sigmoidf_(float x) { return 1.0f / (1.0f + expf(-x)); }

__device__ __forceinline__ unsigned f2tf(float f) {
    unsigned u;
    asm("cvt.rna.tf32.f32 %0, %1;" : "=r"(u) : "f"(f));
    return u;
}

#define MMA(d, A0, A1, A2, A3, B0, B1)                                          \
    asm volatile("mma.sync.aligned.m16n8k8.row.col.f32.tf32.tf32.f32 "          \
                 "{%0,%1,%2,%3},{%4,%5,%6,%7},{%8,%9},{%0,%1,%2,%3};"           \
                 : "+f"(d[0]), "+f"(d[1]), "+f"(d[2]), "+f"(d[3])               \
                 : "r"(A0), "r"(A1), "r"(A2), "r"(A3), "r"(B0), "r"(B1))

// global barrier over all NB CTAs
__device__ __forceinline__ void gsync_all(unsigned& sense) {
    __syncthreads();
    __threadfence();
    unsigned target = sense ^ 1u;
    if (threadIdx.x == 0) {
        unsigned old = atomicAdd(&g_cnt_all, 1u);
        if (old == NB - 1) {
            g_cnt_all = 0;
            __threadfence();
            atomicExch(&g_sense_all, target);
        } else {
            while (atomicAdd(&g_sense_all, 0u) != target) { __nanosleep(128); }
        }
        __threadfence();
    }
    sense = target;
    __syncthreads();
}

// barrier over one group of GSZ CTAs
__device__ __forceinline__ void gsync_grp(int g, unsigned& sense) {
    __syncthreads();
    __threadfence();
    unsigned target = sense ^ 1u;
    if (threadIdx.x == 0) {
        unsigned old = atomicAdd(&g_cnt_grp[g], 1u);
        if (old == GSZ - 1) {
            g_cnt_grp[g] = 0;
            __threadfence();
            atomicExch(&g_sense_grp[g], target);
        } else {
            while (atomicAdd(&g_sense_grp[g], 0u) != target) { __nanosleep(64); }
        }
        __threadfence();
    }
    sense = target;
    __syncthreads();
}

__device__ __forceinline__ void cta_reduce_store(float* SM, float v, float* dst) {
    __syncthreads();
    SM[threadIdx.x] = v;
    __syncthreads();
#pragma unroll
    for (int s = 128; s > 0; s >>= 1) {
        if (threadIdx.x < s) SM[threadIdx.x] += SM[threadIdx.x + s];
        __syncthreads();
    }
    if (threadIdx.x == 0) *dst = SM[0];
    __syncthreads();
}

__global__ void __launch_bounds__(NT) rits_kernel(
    const float* __restrict__ values, const float* __restrict__ masks,
    const float* __restrict__ deltas,
    const float* __restrict__ W_td_h, const float* __restrict__ b_td_h,
    const float* __restrict__ W_td_x, const float* __restrict__ b_td_x,
    const float* __restrict__ W_hist, const float* __restrict__ b_hist,
    const float* __restrict__ W_feat, const float* __restrict__ b_feat,
    const float* __restrict__ W_comb, const float* __restrict__ b_comb,
    const float* __restrict__ W_ih, const float* __restrict__ W_hh,
    const float* __restrict__ b_ih, const float* __restrict__ b_hh,
    float* __restrict__ out)
{
    __shared__ __align__(16) float SM[7168];
    unsigned* Asu = (unsigned*)SM;            // staging A (tf32 bits)
    unsigned* Bsu = (unsigned*)(SM + 4608);   // staging B (tf32 bits)

    const int tid = threadIdx.x;
    const int cta = blockIdx.x;
    const int wid = tid >> 5;
    const int lane = tid & 31;
    const int gid = lane >> 2;   // group-of-4 id within warp (row)
    const int tg = lane & 3;     // thread-in-group

    const int g = cta >> 5;      // group (0..3)
    const int cg = cta & 31;     // cta within group
    const int b0 = g * GROWS;    // first batch row of group

    unsigned gs = *((volatile unsigned*)&g_sense_all);
    unsigned ls = *((volatile unsigned*)&g_sense_grp[g]);

    // ---------- init state + elementwise gamma_x precompute ----------
    for (int i = cta * NT + tid; i < Bn * Hn; i += NB * NT) {
        g_c[i] = 0.0f;
        g_hdec[0][i] = 0.0f;
        g_hdec[1][i] = 0.0f;
    }
    {
        const int n4 = Bn * Tn * Fn / 4;
        const float4* d4p = (const float4*)deltas;
        float4* gx4 = (float4*)g_gx;
        for (int i = cta * NT + tid; i < n4; i += NB * NT) {
            int base = i * 4;
            int kg = base & (Fn - 1);
            float4 d = d4p[i];
            float4 r;
            r.x = expf(-fmaxf(fmaf(d.x, W_td_x[(kg + 0) * Fn + kg + 0], b_td_x[kg + 0]), 0.0f));
            r.y = expf(-fmaxf(fmaf(d.y, W_td_x[(kg + 1) * Fn + kg + 1], b_td_x[kg + 1]), 0.0f));
            r.z = expf(-fmaxf(fmaf(d.z, W_td_x[(kg + 2) * Fn + kg + 2], b_td_x[kg + 2]), 0.0f));
            r.w = expf(-fmaxf(fmaf(d.w, W_td_x[(kg + 3) * Fn + kg + 3], b_td_x[kg + 3]), 0.0f));
            gx4[i] = r;
        }
    }
    gsync_all(gs);

    // ---------- precompute gamma_h (1600 tiles) and alpha (800 tiles) via tf32 mma ----------
    // CTA tile 128x64, warps 4(M)x2(N), warp tile 32x32 (2 m-frags x 4 n-frags)
    {
        const int wm = wid & 3, wn = wid >> 2;
        for (int tt = cta; tt < 2400; tt += NB) {
            float acc[2][4][4];
#pragma unroll
            for (int mf = 0; mf < 2; mf++)
#pragma unroll
                for (int nf = 0; nf < 4; nf++)
#pragma unroll
                    for (int e = 0; e < 4; e++) acc[mf][nf][e] = 0.0f;

            const bool is_gamma = (tt < 1600);
            const int m0 = is_gamma ? (tt >> 3) * 128 : ((tt - 1600) >> 2) * 128;
            const int n0 = is_gamma ? (tt & 7) * 64 : ((tt - 1600) & 3) * 64;
            const int K = is_gamma ? Fn : 2 * Fn;

            for (int k0 = 0; k0 < K; k0 += 32) {
                // stage A: 128x32
#pragma unroll
                for (int q = 0; q < 4; q++) {
                    int idx = tid + q * 256;
                    int r = idx >> 3, c4 = (idx & 7) * 4;
                    float4 v;
                    if (is_gamma) {
                        v = *(const float4*)&deltas[(size_t)(m0 + r) * Fn + k0 + c4];
                    } else {
                        int kg = k0 + c4;
                        if (kg < Fn)
                            v = *(const float4*)&g_gx[(size_t)(m0 + r) * Fn + kg];
                        else
                            v = *(const float4*)&masks[(size_t)(m0 + r) * Fn + (kg - Fn)];
                    }
                    uint4 u = {f2tf(v.x), f2tf(v.y), f2tf(v.z), f2tf(v.w)};
                    *(uint4*)&Asu[r * PIT + c4] = u;
                }
                // stage B: 64x32
#pragma unroll
                for (int q = 0; q < 2; q++) {
                    int idx = tid + q * 256;
                    int r = idx >> 3, c4 = (idx & 7) * 4;
                    float4 v;
                    if (is_gamma)
                        v = *(const float4*)&W_td_h[(size_t)(n0 + r) * Fn + k0 + c4];
                    else
                        v = *(const float4*)&W_comb[(size_t)(n0 + r) * (2 * Fn) + k0 + c4];
                    uint4 u = {f2tf(v.x), f2tf(v.y), f2tf(v.z), f2tf(v.w)};
                    *(uint4*)&Bsu[r * PIT + c4] = u;
                }
                __syncthreads();
#pragma unroll
                for (int ks = 0; ks < 4; ks++) {
                    int kb = ks * 8;
                    unsigned a[2][4], bfr[4][2];
#pragma unroll
                    for (int mf = 0; mf < 2; mf++) {
                        int row = wm * 32 + mf * 16;
                        a[mf][0] = Asu[(row + gid) * PIT + kb + tg];
                        a[mf][1] = Asu[(row + gid + 8) * PIT + kb + tg];
                        a[mf][2] = Asu[(row + gid) * PIT + kb + tg + 4];
                        a[mf][3] = Asu[(row + gid + 8) * PIT + kb + tg + 4];
                    }
#pragma unroll
                    for (int nf = 0; nf < 4; nf++) {
                        int n = wn * 32 + nf * 8;
                        bfr[nf][0] = Bsu[(n + gid) * PIT + kb + tg];
                        bfr[nf][1] = Bsu[(n + gid) * PIT + kb + tg + 4];
                    }
#pragma unroll
                    for (int mf = 0; mf < 2; mf++)
#pragma unroll
                        for (int nf = 0; nf < 4; nf++)
                            MMA(acc[mf][nf], a[mf][0], a[mf][1], a[mf][2], a[mf][3],
                                bfr[nf][0], bfr[nf][1]);
                }
                __syncthreads();
            }
            // epilogue
#pragma unroll
            for (int mf = 0; mf < 2; mf++) {
#pragma unroll
                for (int nf = 0; nf < 4; nf++) {
#pragma unroll
                    for (int e = 0; e < 4; e++) {
                        int bt = m0 + wm * 32 + mf * 16 + gid + ((e >> 1) << 3);
                        int n = n0 + wn * 32 + nf * 8 + 2 * tg + (e & 1);
                        float v = acc[mf][nf][e];
                        if (is_gamma)
                            g_gamma_h[(size_t)bt * Hn + n] =
                                expf(-fmaxf(v + b_td_h[n], 0.0f));
                        else
                            g_alpha[(size_t)bt * Fn + n] = sigmoidf_(v + b_comb[n]);
                    }
                }
            }
        }
    }
    gsync_all(gs);

    // ---------- sequential recurrence (group-local sync) ----------
    for (int t = 0; t < Tn; t++) {
        const float* hdec_r = g_hdec[t & 1];
        float* hdec_w = g_hdec[(t + 1) & 1];

        // ===== P_a: x_h = h_dec @ W_hist^T + b_hist  (group M=64, N=256, K=512) =====
        if (cg < 16) {
            const int n0g = cg * 16;
            const int wm = wid & 3, wn = wid >> 2;   // warp tile 16x8
            float acc[4] = {0.f, 0.f, 0.f, 0.f};
            for (int k0 = 0; k0 < Hn; k0 += 32) {
#pragma unroll
                for (int q = 0; q < 2; q++) {
                    int idx = tid + q * 256;
                    int r = idx >> 3, c4 = (idx & 7) * 4;
                    float4 v = *(const float4*)&hdec_r[(b0 + r) * Hn + k0 + c4];
                    uint4 u = {f2tf(v.x), f2tf(v.y), f2tf(v.z), f2tf(v.w)};
                    *(uint4*)&Asu[r * PIT + c4] = u;
                }
                if (tid < 128) {
                    int r = tid >> 3, c4 = (tid & 7) * 4;
                    float4 v = *(const float4*)&W_hist[(size_t)(n0g + r) * Hn + k0 + c4];
                    uint4 u = {f2tf(v.x), f2tf(v.y), f2tf(v.z), f2tf(v.w)};
                    *(uint4*)&Bsu[r * PIT + c4] = u;
                }
                __syncthreads();
#pragma unroll
                for (int ks = 0; ks < 4; ks++) {
                    int kb = ks * 8;
                    int row = wm * 16;
                    unsigned a0 = Asu[(row + gid) * PIT + kb + tg];
                    unsigned a1 = Asu[(row + gid + 8) * PIT + kb + tg];
                    unsigned a2 = Asu[(row + gid) * PIT + kb + tg + 4];
                    unsigned a3 = Asu[(row + gid + 8) * PIT + kb + tg + 4];
                    int n = wn * 8;
                    unsigned bb0 = Bsu[(n + gid) * PIT + kb + tg];
                    unsigned bb1 = Bsu[(n + gid) * PIT + kb + tg + 4];
                    MMA(acc, a0, a1, a2, a3, bb0, bb1);
                }
                __syncthreads();
            }
            float ls_ = 0.0f;
#pragma unroll
            for (int e = 0; e < 4; e++) {
                int b = b0 + wm * 16 + gid + ((e >> 1) << 3);
                int f = n0g + wn * 8 + 2 * tg + (e & 1);
                float xh = acc[e] + b_hist[f];
                g_xh[b * Fn + f] = xh;
                size_t vi = (size_t)(b * Tn + t) * Fn + f;
                ls_ += fabsf(xh - values[vi]) * masks[vi];
            }
            cta_reduce_store(SM, ls_, &g_l1[t * 64 + g * 16 + cg]);
        }
        gsync_grp(g, ls);

        // ===== P_b: z_h = relu(x_c @ Wf_masked^T + b_feat) + fused epilogue =====
        if (cg < 16) {
            const int n0g = cg * 16;
            const int wm = wid & 3, wn = wid >> 2;
            float acc[4] = {0.f, 0.f, 0.f, 0.f};
            for (int k0 = 0; k0 < Fn; k0 += 32) {
#pragma unroll
                for (int q = 0; q < 2; q++) {
                    int idx = tid + q * 256;
                    int r = idx >> 3, c4 = (idx & 7) * 4;
                    int b = b0 + r;
                    size_t vi = (size_t)(b * Tn + t) * Fn + k0 + c4;
                    float4 m = *(const float4*)&masks[vi];
                    float4 x = *(const float4*)&values[vi];
                    float4 xh = *(const float4*)&g_xh[b * Fn + k0 + c4];
                    uint4 u;
                    u.x = f2tf(m.x * x.x + (1.0f - m.x) * xh.x);
                    u.y = f2tf(m.y * x.y + (1.0f - m.y) * xh.y);
                    u.z = f2tf(m.z * x.z + (1.0f - m.z) * xh.z);
                    u.w = f2tf(m.w * x.w + (1.0f - m.w) * xh.w);
                    *(uint4*)&Asu[r * PIT + c4] = u;
                }
                if (tid < 128) {
                    int r = tid >> 3, c4 = (tid & 7) * 4;
                    int n = n0g + r;
                    float4 v = *(const float4*)&W_feat[(size_t)n * Fn + k0 + c4];
                    int dd = n - (k0 + c4);
                    if (dd == 0) v.x = 0.0f;
                    else if (dd == 1) v.y = 0.0f;
                    else if (dd == 2) v.z = 0.0f;
                    else if (dd == 3) v.w = 0.0f;
                    uint4 u = {f2tf(v.x), f2tf(v.y), f2tf(v.z), f2tf(v.w)};
                    *(uint4*)&Bsu[r * PIT + c4] = u;
                }
                __syncthreads();
#pragma unroll
                for (int ks = 0; ks < 4; ks++) {
                    int kb = ks * 8;
                    int row = wm * 16;
                    unsigned a0 = Asu[(row + gid) * PIT + kb + tg];
                    unsigned a1 = Asu[(row + gid + 8) * PIT + kb + tg];
                    unsigned a2 = Asu[(row + gid) * PIT + kb + tg + 4];
                    unsigned a3 = Asu[(row + gid + 8) * PIT + kb + tg + 4];
                    int n = wn * 8;
                    unsigned bb0 = Bsu[(n + gid) * PIT + kb + tg];
                    unsigned bb1 = Bsu[(n + gid) * PIT + kb + tg + 4];
                    MMA(acc, a0, a1, a2, a3, bb0, bb1);
                }
                __syncthreads();
            }
            float l2s = 0.f, l3s = 0.f, dns = 0.f;
#pragma unroll
            for (int e = 0; e < 4; e++) {
                int b = b0 + wm * 16 + gid + ((e >> 1) << 3);
                int f = n0g + wn * 8 + 2 * tg + (e & 1);
                size_t bt = (size_t)(b * Tn + t);
                float z = fmaxf(acc[e] + b_feat[f], 0.0f);
                float al = g_alpha[bt * Fn + f];
                float xh = g_xh[b * Fn + f];
                float ch = al * z + (1.0f - al) * xh;
                size_t vi = bt * Fn + f;
                float x = values[vi], m = masks[vi];
                float cc = m * x + (1.0f - m) * ch;
                out[vi] = cc;
                g_cc[b * Fn + f] = cc;
                l2s += fabsf(z - x) * m;
                l3s += fabsf(ch - x) * m;
                dns += m;
            }
            cta_reduce_store(SM, l2s, &g_l2[t * 64 + g * 16 + cg]);
            cta_reduce_store(SM, l3s, &g_l3[t * 64 + g * 16 + cg]);
            cta_reduce_store(SM, dns, &g_den[t * 64 + g * 16 + cg]);
        }
        gsync_grp(g, ls);

        // ===== P_c: gates GEMM (M=64, Nvirt=64 = 4 gates x 16 j, K=1024) + LSTM =====
        {
            const int j0 = cg * 16;
            const int wm = wid & 1, wn = wid >> 1;   // warp tile 32x16
            float acc[2][2][4];
#pragma unroll
            for (int mf = 0; mf < 2; mf++)
#pragma unroll
                for (int nf = 0; nf < 2; nf++)
#pragma unroll
                    for (int e = 0; e < 4; e++) acc[mf][nf][e] = 0.0f;

            for (int k0 = 0; k0 < 1024; k0 += 32) {
#pragma unroll
                for (int q = 0; q < 2; q++) {
                    int idx = tid + q * 256;
                    int r = idx >> 3, c4 = (idx & 7) * 4;
                    int b = b0 + r;
                    float4 v;
                    if (k0 < 256)
                        v = *(const float4*)&g_cc[b * Fn + k0 + c4];
                    else if (k0 < 512)
                        v = *(const float4*)&masks[(size_t)(b * Tn + t) * Fn + (k0 - 256) + c4];
                    else
                        v = *(const float4*)&hdec_r[b * Hn + (k0 - 512) + c4];
                    uint4 u = {f2tf(v.x), f2tf(v.y), f2tf(v.z), f2tf(v.w)};
                    *(uint4*)&Asu[r * PIT + c4] = u;
                }
#pragma unroll
                for (int q = 0; q < 2; q++) {
                    int idx = tid + q * 256;
                    int r = idx >> 3, c4 = (idx & 7) * 4;
                    int gate = r >> 4, jl = r & 15;
                    size_t wrow = (size_t)(gate * Hn + j0 + jl);
                    float4 v;
                    if (k0 < 512)
                        v = *(const float4*)&W_ih[wrow * 512 + k0 + c4];
                    else
                        v = *(const float4*)&W_hh[wrow * 512 + (k0 - 512) + c4];
                    uint4 u = {f2tf(v.x), f2tf(v.y), f2tf(v.z), f2tf(v.w)};
                    *(uint4*)&Bsu[r * PIT + c4] = u;
                }
                __syncthreads();
#pragma unroll
                for (int ks = 0; ks < 4; ks++) {
                    int kb = ks * 8;
                    unsigned a[2][4], bfr[2][2];
#pragma unroll
                    for (int mf = 0; mf < 2; mf++) {
                        int row = wm * 32 + mf * 16;
                        a[mf][0] = Asu[(row + gid) * PIT + kb + tg];
                        a[mf][1] = Asu[(row + gid + 8) * PIT + kb + tg];
                        a[mf][2] = Asu[(row + gid) * PIT + kb + tg + 4];
                        a[mf][3] = Asu[(row + gid + 8) * PIT + kb + tg + 4];
                    }
#pragma unroll
                    for (int nf = 0; nf < 2; nf++) {
                        int n = wn * 16 + nf * 8;
                        bfr[nf][0] = Bsu[(n + gid) * PIT + kb + tg];
                        bfr[nf][1] = Bsu[(n + gid) * PIT + kb + tg + 4];
                    }
#pragma unroll
                    for (int mf = 0; mf < 2; mf++)
#pragma unroll
                        for (int nf = 0; nf < 2; nf++)
                            MMA(acc[mf][nf], a[mf][0], a[mf][1], a[mf][2], a[mf][3],
                                bfr[nf][0], bfr[nf][1]);
                }
                __syncthreads();
            }
            // stage accums to smem, then fused LSTM
#pragma unroll
            for (int mf = 0; mf < 2; mf++)
#pragma unroll
                for (int nf = 0; nf < 2; nf++)
#pragma unroll
                    for (int e = 0; e < 4; e++) {
                        int r = wm * 32 + mf * 16 + gid + ((e >> 1) << 3);
                        int v = wn * 16 + nf * 8 + 2 * tg + (e & 1);
                        SM[r * APIT + v] = acc[mf][nf][e];
                    }
            __syncthreads();
#pragma unroll
            for (int q = 0; q < 4; q++) {
                int idx = tid + q * 256;
                int r = idx >> 4, jl = idx & 15;
                int b = b0 + r;
                int j = j0 + jl;
                float ia = SM[r * APIT + jl] + b_ih[0 * Hn + j] + b_hh[0 * Hn + j];
                float fa = SM[r * APIT + 16 + jl] + b_ih[1 * Hn + j] + b_hh[1 * Hn + j];
                float ga = SM[r * APIT + 32 + jl] + b_ih[2 * Hn + j] + b_hh[2 * Hn + j];
                float oa = SM[r * APIT + 48 + jl] + b_ih[3 * Hn + j] + b_hh[3 * Hn + j];
                int ci = b * Hn + j;
                float cn = sigmoidf_(fa) * g_c[ci] + sigmoidf_(ia) * tanhf(ga);
                float hn = sigmoidf_(oa) * tanhf(cn);
                g_c[ci] = cn;
                if (t + 1 < Tn)
                    hdec_w[ci] = hn * g_gamma_h[(size_t)(b * Tn + t + 1) * Hn + j];
                else
                    out[(size_t)Bn * Tn * Fn + ci] = hn;
            }
        }
        gsync_grp(g, ls);
    }

    gsync_all(gs);

    // ---------- final deterministic loss reduction ----------
    if (cta == 0) {
        float v = 0.0f;
        if (tid < Tn) {
            float den = 1e-9f, n1 = 0.f, n2 = 0.f, n3 = 0.f;
            for (int c2 = 0; c2 < 64; c2++) {
                den += g_den[tid * 64 + c2];
                n1 += g_l1[tid * 64 + c2];
                n2 += g_l2[tid * 64 + c2];
                n3 += g_l3[tid * 64 + c2];
            }
            v = (n1 + n2 + n3) / den;
        }
        __syncthreads();
        SM[tid] = v;
        __syncthreads();
#pragma unroll
        for (int s = 128; s > 0; s >>= 1) {
            if (tid < s) SM[tid] += SM[tid + s];
            __syncthreads();
        }
        if (tid == 0) out[(size_t)Bn * Tn * Fn + Bn * Hn] = SM[0] / (3.0f * Tn);
    }
}

extern "C" void kernel_launch(void* const* d_in, const int* in_sizes, int n_in,
                              void* d_out, int out_size) {
    (void)in_sizes; (void)n_in; (void)out_size;
    rits_kernel<<<NB, NT>>>(
        (const float*)d_in[0],  (const float*)d_in[1],  (const float*)d_in[2],
        (const float*)d_in[3],  (const float*)d_in[4],  (const float*)d_in[5],
        (const float*)d_in[6],  (const float*)d_in[7],  (const float*)d_in[8],
        (const float*)d_in[9],  (const float*)d_in[10], (const float*)d_in[11],
        (const float*)d_in[12], (const float*)d_in[13], (const float*)d_in[14],
        (const float*)d_in[15], (const float*)d_in[16],
        (float*)d_out);
}

// round 3
// speedup vs baseline: 3.7599x; 1.7145x over previous
#include <cuda_runtime.h>
#include <math.h>

#define Bn 256
#define Tn 100
#define Fn 256
#define Hn 512
#define NB 128
#define NT 256
#define BT (Bn * Tn)
#define PIT 68
#define STW (128 * PIT)            // stage words: A 64*68 + B 64*68
#define SMEM_WORDS (3 * STW + 256)
#define SMEM_BYTES (SMEM_WORDS * 4)

// ---------------- global scratch (allocation-free rule) ----------------
__device__ unsigned g_dt[(size_t)BT * Fn];        // tf32 deltas
__device__ unsigned g_gxm[(size_t)BT * 2 * Fn];   // [tf32 gamma_x | tf32 mask]
__device__ float    g_gamma_h[(size_t)BT * Hn];
__device__ float    g_alpha[(size_t)BT * Fn];
__device__ unsigned g_Wtdh[Hn * Fn];
__device__ unsigned g_Wcomb[Fn * 2 * Fn];
__device__ unsigned g_Whist[Fn * Hn];
__device__ unsigned g_Wfeat[Fn * Fn];
__device__ unsigned g_Wg[(size_t)4 * Hn * 1024];  // row = j*4+gate, cols [W_ih|W_hh]
__device__ float    g_bg[4 * Hn];
__device__ float    g_xh[Bn * Fn];
__device__ unsigned g_xc[Bn * Fn];                // tf32 x_c
__device__ unsigned g_ccb[Bn * Fn];               // tf32 c_c
__device__ unsigned g_h[2][Bn * Hn];              // tf32 h_dec (double buffer)
__device__ float    g_cst[Bn * Hn];
__device__ float    g_l1[Tn * 64], g_l2[Tn * 64], g_l3[Tn * 64], g_den[Tn * 64];
__device__ unsigned g_cnt, g_sense;

__device__ __forceinline__ float sigmoidf_(float x) { return 1.0f / (1.0f + expf(-x)); }

__device__ __forceinline__ unsigned f2tf(float f) {
    unsigned u;
    asm("cvt.rna.tf32.f32 %0, %1;" : "=r"(u) : "f"(f));
    return u;
}
__device__ __forceinline__ uint4 tf4(float4 v) {
    uint4 u = {f2tf(v.x), f2tf(v.y), f2tf(v.z), f2tf(v.w)};
    return u;
}

#define MMA(d, A0, A1, A2, A3, B0, B1)                                          \
    asm volatile("mma.sync.aligned.m16n8k8.row.col.f32.tf32.tf32.f32 "          \
                 "{%0,%1,%2,%3},{%4,%5,%6,%7},{%8,%9},{%0,%1,%2,%3};"           \
                 : "+f"(d[0]), "+f"(d[1]), "+f"(d[2]), "+f"(d[3])               \
                 : "r"(A0), "r"(A1), "r"(A2), "r"(A3), "r"(B0), "r"(B1))

#define CP16(woff, p)                                                           \
    asm volatile("cp.async.cg.shared.global [%0], [%1], 16;"                    \
                 :: "r"(sbase + (unsigned)((woff) << 2)), "l"(p) : "memory")
#define CMT   asm volatile("cp.async.commit_group;" ::: "memory")
#define WAIT2 asm volatile("cp.async.wait_group 2;" ::: "memory")
#define WAIT0 asm volatile("cp.async.wait_group 0;" ::: "memory")

// global barrier over all NB CTAs (all co-resident: NB=128 <= 152 SMs, 1 CTA/SM)
__device__ __forceinline__ void gsync(unsigned& sense) {
    __syncthreads();
    unsigned target = sense ^ 1u;
    if (threadIdx.x == 0) {
        __threadfence();
        unsigned old = atomicAdd(&g_cnt, 1u);
        if (old == NB - 1) {
            g_cnt = 0;
            __threadfence();
            atomicExch(&g_sense, target);
        } else {
            while (*((volatile unsigned*)&g_sense) != target) { }
        }
        __threadfence();
    }
    sense = target;
    __syncthreads();
}

__device__ __forceinline__ void cta_reduce_store(float* RED, float v, float* dst) {
    __syncthreads();
    RED[threadIdx.x] = v;
    __syncthreads();
#pragma unroll
    for (int s = 128; s > 0; s >>= 1) {
        if (threadIdx.x < s) RED[threadIdx.x] += RED[threadIdx.x + s];
        __syncthreads();
    }
    if (threadIdx.x == 0) *dst = RED[0];
    __syncthreads();
}

// 64x64 tile MMA over one 64-K stage; warps 4(M)x2(N), warp tile 16x32
__device__ __forceinline__ void mma64(const unsigned* As, const unsigned* Bs,
                                      float acc[4][4], int wm, int wn, int gid, int tg) {
#pragma unroll
    for (int ks = 0; ks < 8; ks++) {
        int kb = ks * 8;
        unsigned a0 = As[(wm * 16 + gid) * PIT + kb + tg];
        unsigned a1 = As[(wm * 16 + gid + 8) * PIT + kb + tg];
        unsigned a2 = As[(wm * 16 + gid) * PIT + kb + tg + 4];
        unsigned a3 = As[(wm * 16 + gid + 8) * PIT + kb + tg + 4];
#pragma unroll
        for (int nf = 0; nf < 4; nf++) {
            int n = wn * 32 + nf * 8;
            unsigned b0 = Bs[(n + gid) * PIT + kb + tg];
            unsigned b1 = Bs[(n + gid) * PIT + kb + tg + 4];
            MMA(acc[nf], a0, a1, a2, a3, b0, b1);
        }
    }
}
// 32x32 tile MMA; warps 2(M)x4(N), warp tile 16x8
__device__ __forceinline__ void mma32(const unsigned* As, const unsigned* Bs,
                                      float acc[4], int wm, int wn, int gid, int tg) {
#pragma unroll
    for (int ks = 0; ks < 8; ks++) {
        int kb = ks * 8;
        unsigned a0 = As[(wm * 16 + gid) * PIT + kb + tg];
        unsigned a1 = As[(wm * 16 + gid + 8) * PIT + kb + tg];
        unsigned a2 = As[(wm * 16 + gid) * PIT + kb + tg + 4];
        unsigned a3 = As[(wm * 16 + gid + 8) * PIT + kb + tg + 4];
        int n = wn * 8;
        unsigned b0 = Bs[(n + gid) * PIT + kb + tg];
        unsigned b1 = Bs[(n + gid) * PIT + kb + tg + 4];
        MMA(acc, a0, a1, a2, a3, b0, b1);
    }
}

__global__ void __launch_bounds__(NT, 1) rits_kernel(
    const float* __restrict__ values, const float* __restrict__ masks,
    const float* __restrict__ deltas,
    const float* __restrict__ W_td_h, const float* __restrict__ b_td_h,
    const float* __restrict__ W_td_x, const float* __restrict__ b_td_x,
    const float* __restrict__ W_hist, const float* __restrict__ b_hist,
    const float* __restrict__ W_feat, const float* __restrict__ b_feat,
    const float* __restrict__ W_comb, const float* __restrict__ b_comb,
    const float* __restrict__ W_ih, const float* __restrict__ W_hh,
    const float* __restrict__ b_ih, const float* __restrict__ b_hh,
    float* __restrict__ out)
{
    extern __shared__ unsigned SHu[];
    float* RED = (float*)(SHu + 3 * STW);
    unsigned sbase = (unsigned)__cvta_generic_to_shared(SHu);

    const int tid = threadIdx.x;
    const int cta = blockIdx.x;
    const int wid = tid >> 5;
    const int lane = tid & 31;
    const int gid = lane >> 2;
    const int tg = lane & 3;
    const int wm4 = wid & 3, wn4 = wid >> 2;   // 64-tile warp grid
    const int wm2 = wid & 1, wn2 = wid >> 1;   // 32-tile warp grid

    unsigned sense = *((volatile unsigned*)&g_sense);

    // =================== init: state + tf32 pre-conversion ===================
    for (int i = cta * NT + tid; i < Bn * Hn; i += NB * NT) {
        g_cst[i] = 0.0f;
        g_h[0][i] = 0u;
        g_h[1][i] = 0u;
    }
    // deltas -> g_dt; gamma_x + masks -> g_gxm
    {
        const float4* d4 = (const float4*)deltas;
        const float4* m4 = (const float4*)masks;
        for (int i = cta * NT + tid; i < BT * Fn / 4; i += NB * NT) {
            int f = (i * 4) & (Fn - 1);
            size_t row = (size_t)(i >> 6);
            float4 d = d4[i];
            ((uint4*)g_dt)[i] = tf4(d);
            float4 gx;
            gx.x = expf(-fmaxf(fmaf(d.x, W_td_x[(f + 0) * Fn + f + 0], b_td_x[f + 0]), 0.f));
            gx.y = expf(-fmaxf(fmaf(d.y, W_td_x[(f + 1) * Fn + f + 1], b_td_x[f + 1]), 0.f));
            gx.z = expf(-fmaxf(fmaf(d.z, W_td_x[(f + 2) * Fn + f + 2], b_td_x[f + 2]), 0.f));
            gx.w = expf(-fmaxf(fmaf(d.w, W_td_x[(f + 3) * Fn + f + 3], b_td_x[f + 3]), 0.f));
            *(uint4*)&g_gxm[row * 512 + f] = tf4(gx);
            *(uint4*)&g_gxm[row * 512 + 256 + f] = tf4(m4[i]);
        }
    }
    // weight conversions
    for (int i = cta * NT + tid; i < Hn * Fn / 4; i += NB * NT)
        ((uint4*)g_Wtdh)[i] = tf4(((const float4*)W_td_h)[i]);
    for (int i = cta * NT + tid; i < Fn * 2 * Fn / 4; i += NB * NT)
        ((uint4*)g_Wcomb)[i] = tf4(((const float4*)W_comb)[i]);
    for (int i = cta * NT + tid; i < Fn * Hn / 4; i += NB * NT)
        ((uint4*)g_Whist)[i] = tf4(((const float4*)W_hist)[i]);
    for (int i = cta * NT + tid; i < Fn * Fn / 4; i += NB * NT) {
        int n = (i * 4) >> 8, k = (i * 4) & 255;
        float4 v = ((const float4*)W_feat)[i];
        int dd = n - k;
        if (dd == 0) v.x = 0.f; else if (dd == 1) v.y = 0.f;
        else if (dd == 2) v.z = 0.f; else if (dd == 3) v.w = 0.f;
        ((uint4*)g_Wfeat)[i] = tf4(v);
    }
    for (int i = cta * NT + tid; i < 4 * Hn * 1024 / 4; i += NB * NT) {
        int wr = i >> 8;                 // row (j*4+gate)
        int c4 = (i & 255) * 4;
        int j = wr >> 2, gate = wr & 3;
        const float* src = (c4 < 512) ? &W_ih[(size_t)(gate * Hn + j) * 512 + c4]
                                      : &W_hh[(size_t)(gate * Hn + j) * 512 + (c4 - 512)];
        ((uint4*)g_Wg)[i] = tf4(*(const float4*)src);
    }
    for (int i = cta * NT + tid; i < 4 * Hn; i += NB * NT) {
        int j = i >> 2, gate = i & 3;
        g_bg[i] = b_ih[gate * Hn + j] + b_hh[gate * Hn + j];
    }
    gsync(sense);

    // =================== precompute gamma_h (3200 tiles) + alpha (1600) ===================
    for (int tt = cta; tt < 4800; tt += NB) {
        float acc[4][4];
#pragma unroll
        for (int nf = 0; nf < 4; nf++)
#pragma unroll
            for (int e = 0; e < 4; e++) acc[nf][e] = 0.0f;

        const bool isg = (tt < 3200);
        const int u = isg ? tt : tt - 3200;
        const int m0 = isg ? (u >> 3) * 64 : (u >> 2) * 64;
        const int n0 = isg ? (u & 7) * 64 : (u & 3) * 64;
        const int NI = isg ? 4 : 8;      // K=256 or 512, chunks of 64
        const int KROW = isg ? Fn : 512;

#define LOAD_PRE(k0, s) do {                                                    \
        int aoff = (s) * STW, boff = aoff + 64 * PIT;                           \
        _Pragma("unroll")                                                       \
        for (int jj = 0; jj < 4; jj++) {                                        \
            int cid = tid + jj * 256;                                           \
            int r = cid >> 4, q = cid & 15;                                     \
            int k = (k0) + q * 4;                                               \
            const unsigned* src = isg ? (g_dt + (size_t)(m0 + r) * Fn + k)      \
                                      : (g_gxm + (size_t)(m0 + r) * 512 + k);   \
            CP16(aoff + r * PIT + q * 4, src);                                  \
        }                                                                       \
        _Pragma("unroll")                                                       \
        for (int jj = 0; jj < 4; jj++) {                                        \
            int cid = tid + jj * 256;                                           \
            int r = cid >> 4, q = cid & 15;                                     \
            int k = (k0) + q * 4;                                               \
            const unsigned* src = isg ? (g_Wtdh + (size_t)(n0 + r) * Fn + k)    \
                                      : (g_Wcomb + (size_t)(n0 + r) * 512 + k); \
            CP16(boff + r * PIT + q * 4, src);                                  \
        }                                                                       \
    } while (0)

        LOAD_PRE(0, 0); CMT;
        LOAD_PRE(64, 1); CMT;
        for (int i = 0; i < NI; i++) {
            if (i + 2 < NI) LOAD_PRE((i + 2) * 64, (i + 2) % 3);
            CMT; WAIT2;
            __syncthreads();
            int s = i % 3;
            mma64(SHu + s * STW, SHu + s * STW + 64 * PIT, acc, wm4, wn4, gid, tg);
            __syncthreads();
        }
        WAIT0;
        (void)KROW;
#pragma unroll
        for (int nf = 0; nf < 4; nf++) {
#pragma unroll
            for (int e = 0; e < 4; e++) {
                int bt = m0 + wm4 * 16 + gid + ((e >> 1) << 3);
                int n = n0 + wn4 * 32 + nf * 8 + 2 * tg + (e & 1);
                float v = acc[nf][e];
                if (isg)
                    g_gamma_h[(size_t)bt * Hn + n] = expf(-fmaxf(v + b_td_h[n], 0.f));
                else
                    g_alpha[(size_t)bt * Fn + n] = sigmoidf_(v + b_comb[n]);
            }
        }
    }
    gsync(sense);

    // =================== sequential recurrence ===================
    for (int t = 0; t < Tn; t++) {
        const int par = t & 1, nxt = (t + 1) & 1;

        // ===== P_a: x_h = h_dec @ W_hist^T (256x256xK512), 64 CTAs tile 32x32 =====
        if (cta < 64) {
            const int m0 = (cta >> 3) * 32;
            const int n0 = (cta & 7) * 32;
            float acc[4] = {0.f, 0.f, 0.f, 0.f};
#define LOAD_PA(k0, s) do {                                                     \
            int aoff = (s) * STW, boff = aoff + 32 * PIT;                       \
            _Pragma("unroll")                                                   \
            for (int jj = 0; jj < 2; jj++) {                                    \
                int cid = tid + jj * 256;                                       \
                int r = cid >> 4, q = cid & 15;                                 \
                int k = (k0) + q * 4;                                           \
                CP16(aoff + r * PIT + q * 4, g_h[par] + (m0 + r) * Hn + k);     \
                CP16(boff + r * PIT + q * 4, g_Whist + (n0 + r) * Hn + k);      \
            }                                                                   \
        } while (0)
            LOAD_PA(0, 0); CMT;
            LOAD_PA(64, 1); CMT;
            for (int i = 0; i < 8; i++) {
                if (i + 2 < 8) LOAD_PA((i + 2) * 64, (i + 2) % 3);
                CMT; WAIT2;
                __syncthreads();
                int s = i % 3;
                mma32(SHu + s * STW, SHu + s * STW + 32 * PIT, acc, wm2, wn2, gid, tg);
                __syncthreads();
            }
            WAIT0;
            float ls = 0.0f;
#pragma unroll
            for (int e = 0; e < 4; e++) {
                int b = m0 + wm2 * 16 + gid + ((e >> 1) << 3);
                int f = n0 + wn2 * 8 + 2 * tg + (e & 1);
                float xh = acc[e] + b_hist[f];
                g_xh[b * Fn + f] = xh;
                size_t vi = (size_t)(b * Tn + t) * Fn + f;
                float x = values[vi], m = masks[vi];
                ls += fabsf(xh - x) * m;
                g_xc[b * Fn + f] = f2tf(m * x + (1.0f - m) * xh);
            }
            cta_reduce_store(RED, ls, &g_l1[t * 64 + cta]);
        }
        gsync(sense);

        // ===== P_b: z_h = relu(x_c @ Wf^T) (256x256x256), 64 CTAs tile 32x32 =====
        if (cta < 64) {
            const int m0 = (cta >> 3) * 32;
            const int n0 = (cta & 7) * 32;
            float acc[4] = {0.f, 0.f, 0.f, 0.f};
#define LOAD_PB(k0, s) do {                                                     \
            int aoff = (s) * STW, boff = aoff + 32 * PIT;                       \
            _Pragma("unroll")                                                   \
            for (int jj = 0; jj < 2; jj++) {                                    \
                int cid = tid + jj * 256;                                       \
                int r = cid >> 4, q = cid & 15;                                 \
                int k = (k0) + q * 4;                                           \
                CP16(aoff + r * PIT + q * 4, g_xc + (m0 + r) * Fn + k);         \
                CP16(boff + r * PIT + q * 4, g_Wfeat + (n0 + r) * Fn + k);      \
            }                                                                   \
        } while (0)
            LOAD_PB(0, 0); CMT;
            LOAD_PB(64, 1); CMT;
            for (int i = 0; i < 4; i++) {
                if (i + 2 < 4) LOAD_PB((i + 2) * 64, (i + 2) % 3);
                CMT; WAIT2;
                __syncthreads();
                int s = i % 3;
                mma32(SHu + s * STW, SHu + s * STW + 32 * PIT, acc, wm2, wn2, gid, tg);
                __syncthreads();
            }
            WAIT0;
            float l2s = 0.f, l3s = 0.f, dns = 0.f;
#pragma unroll
            for (int e = 0; e < 4; e++) {
                int b = m0 + wm2 * 16 + gid + ((e >> 1) << 3);
                int f = n0 + wn2 * 8 + 2 * tg + (e & 1);
                size_t bt = (size_t)(b * Tn + t);
                float z = fmaxf(acc[e] + b_feat[f], 0.0f);
                float al = g_alpha[bt * Fn + f];
                float xh = g_xh[b * Fn + f];
                float ch = al * z + (1.0f - al) * xh;
                size_t vi = bt * Fn + f;
                float x = values[vi], m = masks[vi];
                float cc = m * x + (1.0f - m) * ch;
                out[vi] = cc;
                g_ccb[b * Fn + f] = f2tf(cc);
                l2s += fabsf(z - x) * m;
                l3s += fabsf(ch - x) * m;
                dns += m;
            }
            cta_reduce_store(RED, l2s, &g_l2[t * 64 + cta]);
            cta_reduce_store(RED, l3s, &g_l3[t * 64 + cta]);
            cta_reduce_store(RED, dns, &g_den[t * 64 + cta]);
        }
        gsync(sense);

        // ===== P_c: gates (256 x 2048 x 1024), 128 CTAs tile 64x64 + fused LSTM =====
        {
            const int m0 = (cta >> 5) * 64;
            const int w0 = (cta & 31) * 64;   // g_Wg row base
            const int j0 = (cta & 31) * 16;   // H-column base
            float acc[4][4];
#pragma unroll
            for (int nf = 0; nf < 4; nf++)
#pragma unroll
                for (int e = 0; e < 4; e++) acc[nf][e] = 0.0f;

#define LOAD_PC(k0, s) do {                                                     \
            int aoff = (s) * STW, boff = aoff + 64 * PIT;                       \
            _Pragma("unroll")                                                   \
            for (int jj = 0; jj < 4; jj++) {                                    \
                int cid = tid + jj * 256;                                       \
                int r = cid >> 4, q = cid & 15;                                 \
                int k = (k0) + q * 4;                                           \
                int b = m0 + r;                                                 \
                const unsigned* src;                                            \
                if (k < 256)      src = g_ccb + b * Fn + k;                     \
                else if (k < 512) src = g_gxm + ((size_t)b * Tn + t) * 512 + k; \
                else              src = g_h[par] + b * Hn + (k - 512);          \
                CP16(aoff + r * PIT + q * 4, src);                              \
            }                                                                   \
            _Pragma("unroll")                                                   \
            for (int jj = 0; jj < 4; jj++) {                                    \
                int cid = tid + jj * 256;                                       \
                int r = cid >> 4, q = cid & 15;                                 \
                int k = (k0) + q * 4;                                           \
                CP16(boff + r * PIT + q * 4, g_Wg + (size_t)(w0 + r) * 1024 + k); \
            }                                                                   \
        } while (0)
            LOAD_PC(0, 0); CMT;
            LOAD_PC(64, 1); CMT;
            for (int i = 0; i < 16; i++) {
                if (i + 2 < 16) LOAD_PC((i + 2) * 64, (i + 2) % 3);
                CMT; WAIT2;
                __syncthreads();
                int s = i % 3;
                mma64(SHu + s * STW, SHu + s * STW + 64 * PIT, acc, wm4, wn4, gid, tg);
                __syncthreads();
            }
            WAIT0;
            // stage accums (reuse stage 0), then fused LSTM
            float* EP = (float*)SHu;
#pragma unroll
            for (int nf = 0; nf < 4; nf++)
#pragma unroll
                for (int e = 0; e < 4; e++) {
                    int r = wm4 * 16 + gid + ((e >> 1) << 3);
                    int cL = wn4 * 32 + nf * 8 + 2 * tg + (e & 1);
                    EP[r * PIT + cL] = acc[nf][e];
                }
            __syncthreads();
#pragma unroll
            for (int q = 0; q < 4; q++) {
                int idx = tid + q * 256;
                int r = idx >> 4, jl = idx & 15;
                int b = m0 + r;
                int j = j0 + jl;
                float ia = EP[r * PIT + jl * 4 + 0] + g_bg[j * 4 + 0];
                float fa = EP[r * PIT + jl * 4 + 1] + g_bg[j * 4 + 1];
                float ga = EP[r * PIT + jl * 4 + 2] + g_bg[j * 4 + 2];
                float oa = EP[r * PIT + jl * 4 + 3] + g_bg[j * 4 + 3];
                int ci = b * Hn + j;
                float cn = sigmoidf_(fa) * g_cst[ci] + sigmoidf_(ia) * tanhf(ga);
                float hn = sigmoidf_(oa) * tanhf(cn);
                g_cst[ci] = cn;
                if (t + 1 < Tn)
                    g_h[nxt][ci] = f2tf(hn * g_gamma_h[((size_t)b * Tn + t + 1) * Hn + j]);
                else
                    out[(size_t)Bn * Tn * Fn + ci] = hn;
            }
            __syncthreads();
        }
        gsync(sense);
    }

    // =================== final deterministic loss reduction ===================
    if (cta == 0) {
        float v = 0.0f;
        if (tid < Tn) {
            float den = 1e-9f, n1 = 0.f, n2 = 0.f, n3 = 0.f;
            for (int c2 = 0; c2 < 64; c2++) {
                den += g_den[tid * 64 + c2];
                n1 += g_l1[tid * 64 + c2];
                n2 += g_l2[tid * 64 + c2];
                n3 += g_l3[tid * 64 + c2];
            }
            v = (n1 + n2 + n3) / den;
        }
        __syncthreads();
        RED[tid] = v;
        __syncthreads();
#pragma unroll
        for (int s = 128; s > 0; s >>= 1) {
            if (tid < s) RED[tid] += RED[tid + s];
            __syncthreads();
        }
        if (tid == 0) out[(size_t)Bn * Tn * Fn + Bn * Hn] = RED[0] / (3.0f * Tn);
    }
}

extern "C" void kernel_launch(void* const* d_in, const int* in_sizes, int n_in,
                              void* d_out, int out_size) {
    (void)in_sizes; (void)n_in; (void)out_size;
    static int configured = 0;
    if (!configured) {
        cudaFuncSetAttribute(rits_kernel, cudaFuncAttributeMaxDynamicSharedMemorySize,
                             SMEM_BYTES);
        configured = 1;
    }
    rits_kernel<<<NB, NT, SMEM_BYTES>>>(
        (const float*)d_in[0],  (const float*)d_in[1],  (const float*)d_in[2],
        (const float*)d_in[3],  (const float*)d_in[4],  (const float*)d_in[5],
        (const float*)d_in[6],  (const float*)d_in[7],  (const float*)d_in[8],
        (const float*)d_in[9],  (const float*)d_in[10], (const float*)d_in[11],
        (const float*)d_in[12], (const float*)d_in[13], (const float*)d_in[14],
        (const float*)d_in[15], (const float*)d_in[16],
        (float*)d_out);
}

// round 6
// speedup vs baseline: 4.1253x; 1.0972x over previous
#include <cuda_runtime.h>
#include <math.h>

#define Bn 256
#define Tn 100
#define Fn 256
#define Hn 512
#define NB 128
#define NT 256
#define BT (Bn * Tn)
#define PIT 68
#define STW (128 * PIT)            // stage words: A 64*68 + B 64*68
#define NSTG 4
#define SMEM_WORDS (NSTG * STW + 256)
#define SMEM_BYTES (SMEM_WORDS * 4)

// ---------------- global scratch (allocation-free rule) ----------------
__device__ unsigned g_dt[(size_t)BT * Fn];        // tf32 deltas
__device__ unsigned g_gxm[(size_t)BT * 2 * Fn];   // [tf32 gamma_x | tf32 mask]
__device__ float    g_gamma_h[(size_t)BT * Hn];
__device__ float    g_alpha[(size_t)BT * Fn];
__device__ unsigned g_Wtdh[Hn * Fn];
__device__ unsigned g_Wcomb[Fn * 2 * Fn];
__device__ unsigned g_Whist[Fn * Hn];
__device__ unsigned g_Wfeat[Fn * Fn];
__device__ unsigned g_Wg[(size_t)4 * Hn * 1024];  // row = j*4+gate, cols [W_ih|W_hh]
__device__ float    g_bg[4 * Hn];
__device__ float    g_xh[Bn * Fn];
__device__ unsigned g_xc[Bn * Fn];                // tf32 x_c
__device__ unsigned g_ccb[Bn * Fn];               // tf32 c_c
__device__ unsigned g_h[2][Bn * Hn];              // tf32 h_dec (double buffer)
__device__ float    g_cst[Bn * Hn];
__device__ float    g_l1[Tn * 64], g_l2[Tn * 64], g_l3[Tn * 64], g_den[Tn * 64];
__device__ unsigned g_cnt, g_sense;
// dataflow counters (monotonic within a launch; reset at kernel end)
__device__ unsigned g_cnt_h[4];    // P_c arrivals per group (32/step)
__device__ unsigned g_cnt_xh[8];   // P_a arrivals per 32-row block (8/step)
__device__ unsigned g_cnt_cc[4];   // P_b arrivals per group (16/step)

__device__ __forceinline__ float sigmoidf_(float x) { return 1.0f / (1.0f + expf(-x)); }

__device__ __forceinline__ unsigned f2tf(float f) {
    unsigned u;
    asm("cvt.rna.tf32.f32 %0, %1;" : "=r"(u) : "f"(f));
    return u;
}
__device__ __forceinline__ uint4 tf4(float4 v) {
    uint4 u = {f2tf(v.x), f2tf(v.y), f2tf(v.z), f2tf(v.w)};
    return u;
}

#define MMA(d, A0, A1, A2, A3, B0, B1)                                          \
    asm volatile("mma.sync.aligned.m16n8k8.row.col.f32.tf32.tf32.f32 "          \
                 "{%0,%1,%2,%3},{%4,%5,%6,%7},{%8,%9},{%0,%1,%2,%3};"           \
                 : "+f"(d[0]), "+f"(d[1]), "+f"(d[2]), "+f"(d[3])               \
                 : "r"(A0), "r"(A1), "r"(A2), "r"(A3), "r"(B0), "r"(B1))

#define CP16(woff, p)                                                           \
    asm volatile("cp.async.cg.shared.global [%0], [%1], 16;"                    \
                 :: "r"(sbase + (unsigned)((woff) << 2)), "l"(p) : "memory")
#define CMT   asm volatile("cp.async.commit_group;" ::: "memory")
#define WAIT2 asm volatile("cp.async.wait_group 2;" ::: "memory")

// ---------------- sync primitives ----------------
// Global barrier (3x per launch). All threads release-fence BEFORE the bar so
// thread 0's arrival publishes everyone's stores.
__device__ __forceinline__ void gsync(unsigned& sense) {
    __threadfence();               // release (all threads)
    __syncthreads();
    unsigned target = sense ^ 1u;
    if (threadIdx.x == 0) {
        unsigned old = atomicAdd(&g_cnt, 1u);
        if (old == NB - 1) {
            g_cnt = 0;
            __threadfence();
            atomicExch(&g_sense, target);
        } else {
            while (atomicAdd(&g_sense, 0u) != target) { __nanosleep(128); }
        }
        __threadfence();           // acquire
    }
    sense = target;
    __syncthreads();
}

// dataflow consumer: wait until *cnt >= target, then acquire (CCTL.IVALL
// invalidates this SM's L1 for the LDG epilogue paths)
__device__ __forceinline__ void wait_ge(unsigned* cnt, unsigned target) {
    if (threadIdx.x == 0) {
        while (atomicAdd(cnt, 0u) < target) { __nanosleep(64); }
        __threadfence();           // acquire
    }
    __syncthreads();
}
// dataflow producer: release ALL threads' stores, then publish
__device__ __forceinline__ void arrive(unsigned* cnt) {
    __threadfence();               // release (all threads)
    __syncthreads();
    if (threadIdx.x == 0) atomicAdd(cnt, 1u);
}

__device__ __forceinline__ float wredsum(float v) {
#pragma unroll
    for (int o = 16; o; o >>= 1) v += __shfl_xor_sync(0xffffffffu, v, o);
    return v;
}

// 64x64 tile MMA over one 64-K stage; warps 4(M)x2(N), warp tile 16x32
__device__ __forceinline__ void mma64(const unsigned* As, const unsigned* Bs,
                                      float acc[4][4], int wm, int wn, int gid, int tg) {
#pragma unroll
    for (int ks = 0; ks < 8; ks++) {
        int kb = ks * 8;
        unsigned a0 = As[(wm * 16 + gid) * PIT + kb + tg];
        unsigned a1 = As[(wm * 16 + gid + 8) * PIT + kb + tg];
        unsigned a2 = As[(wm * 16 + gid) * PIT + kb + tg + 4];
        unsigned a3 = As[(wm * 16 + gid + 8) * PIT + kb + tg + 4];
#pragma unroll
        for (int nf = 0; nf < 4; nf++) {
            int n = wn * 32 + nf * 8;
            unsigned b0 = Bs[(n + gid) * PIT + kb + tg];
            unsigned b1 = Bs[(n + gid) * PIT + kb + tg + 4];
            MMA(acc[nf], a0, a1, a2, a3, b0, b1);
        }
    }
}
// 32x32 tile MMA; warps 2(M)x4(N), warp tile 16x8
__device__ __forceinline__ void mma32(const unsigned* As, const unsigned* Bs,
                                      float acc[4], int wm, int wn, int gid, int tg) {
#pragma unroll
    for (int ks = 0; ks < 8; ks++) {
        int kb = ks * 8;
        unsigned a0 = As[(wm * 16 + gid) * PIT + kb + tg];
        unsigned a1 = As[(wm * 16 + gid + 8) * PIT + kb + tg];
        unsigned a2 = As[(wm * 16 + gid) * PIT + kb + tg + 4];
        unsigned a3 = As[(wm * 16 + gid + 8) * PIT + kb + tg + 4];
        int n = wn * 8;
        unsigned b0 = Bs[(n + gid) * PIT + kb + tg];
        unsigned b1 = Bs[(n + gid) * PIT + kb + tg + 4];
        MMA(acc, a0, a1, a2, a3, b0, b1);
    }
}

__global__ void __launch_bounds__(NT, 1) rits_kernel(
    const float* __restrict__ values, const float* __restrict__ masks,
    const float* __restrict__ deltas,
    const float* __restrict__ W_td_h, const float* __restrict__ b_td_h,
    const float* __restrict__ W_td_x, const float* __restrict__ b_td_x,
    const float* __restrict__ W_hist, const float* __restrict__ b_hist,
    const float* __restrict__ W_feat, const float* __restrict__ b_feat,
    const float* __restrict__ W_comb, const float* __restrict__ b_comb,
    const float* __restrict__ W_ih, const float* __restrict__ W_hh,
    const float* __restrict__ b_ih, const float* __restrict__ b_hh,
    float* __restrict__ out)
{
    extern __shared__ unsigned SHu[];
    float* RED = (float*)(SHu + NSTG * STW);
    unsigned sbase = (unsigned)__cvta_generic_to_shared(SHu);

    const int tid = threadIdx.x;
    const int cta = blockIdx.x;
    const int wid = tid >> 5;
    const int lane = tid & 31;
    const int gid = lane >> 2;
    const int tg = lane & 3;
    const int wm4 = wid & 3, wn4 = wid >> 2;   // 64-tile warp grid
    const int wm2 = wid & 1, wn2 = wid >> 1;   // 32-tile warp grid

    const int g = cta >> 5;       // group 0..3 (owns 64 batch rows)
    const int cg = cta & 31;      // cta within group
    const int b0 = g * 64;

    unsigned sense = *((volatile unsigned*)&g_sense);

    // =================== init: state + tf32 pre-conversion ===================
    for (int i = cta * NT + tid; i < Bn * Hn; i += NB * NT) {
        g_cst[i] = 0.0f;
        g_h[0][i] = 0u;
        g_h[1][i] = 0u;
    }
    {
        const float4* d4 = (const float4*)deltas;
        const float4* m4 = (const float4*)masks;
        for (int i = cta * NT + tid; i < BT * Fn / 4; i += NB * NT) {
            int f = (i * 4) & (Fn - 1);
            size_t row = (size_t)(i >> 6);
            float4 d = d4[i];
            ((uint4*)g_dt)[i] = tf4(d);
            float4 gx;
            gx.x = expf(-fmaxf(fmaf(d.x, W_td_x[(f + 0) * Fn + f + 0], b_td_x[f + 0]), 0.f));
            gx.y = expf(-fmaxf(fmaf(d.y, W_td_x[(f + 1) * Fn + f + 1], b_td_x[f + 1]), 0.f));
            gx.z = expf(-fmaxf(fmaf(d.z, W_td_x[(f + 2) * Fn + f + 2], b_td_x[f + 2]), 0.f));
            gx.w = expf(-fmaxf(fmaf(d.w, W_td_x[(f + 3) * Fn + f + 3], b_td_x[f + 3]), 0.f));
            *(uint4*)&g_gxm[row * 512 + f] = tf4(gx);
            *(uint4*)&g_gxm[row * 512 + 256 + f] = tf4(m4[i]);
        }
    }
    for (int i = cta * NT + tid; i < Hn * Fn / 4; i += NB * NT)
        ((uint4*)g_Wtdh)[i] = tf4(((const float4*)W_td_h)[i]);
    for (int i = cta * NT + tid; i < Fn * 2 * Fn / 4; i += NB * NT)
        ((uint4*)g_Wcomb)[i] = tf4(((const float4*)W_comb)[i]);
    for (int i = cta * NT + tid; i < Fn * Hn / 4; i += NB * NT)
        ((uint4*)g_Whist)[i] = tf4(((const float4*)W_hist)[i]);
    for (int i = cta * NT + tid; i < Fn * Fn / 4; i += NB * NT) {
        int n = (i * 4) >> 8, k = (i * 4) & 255;
        float4 v = ((const float4*)W_feat)[i];
        int dd = n - k;
        if (dd == 0) v.x = 0.f; else if (dd == 1) v.y = 0.f;
        else if (dd == 2) v.z = 0.f; else if (dd == 3) v.w = 0.f;
        ((uint4*)g_Wfeat)[i] = tf4(v);
    }
    for (int i = cta * NT + tid; i < 4 * Hn * 1024 / 4; i += NB * NT) {
        int wr = i >> 8;
        int c4 = (i & 255) * 4;
        int j = wr >> 2, gate = wr & 3;
        const float* src = (c4 < 512) ? &W_ih[(size_t)(gate * Hn + j) * 512 + c4]
                                      : &W_hh[(size_t)(gate * Hn + j) * 512 + (c4 - 512)];
        ((uint4*)g_Wg)[i] = tf4(*(const float4*)src);
    }
    for (int i = cta * NT + tid; i < 4 * Hn; i += NB * NT) {
        int j = i >> 2, gate = i & 3;
        g_bg[i] = b_ih[gate * Hn + j] + b_hh[gate * Hn + j];
    }
    gsync(sense);

    // =================== precompute gamma_h (3200 tiles) + alpha (1600) ===================
    for (int tt = cta; tt < 4800; tt += NB) {
        float acc[4][4];
#pragma unroll
        for (int nf = 0; nf < 4; nf++)
#pragma unroll
            for (int e = 0; e < 4; e++) acc[nf][e] = 0.0f;

        const bool isg = (tt < 3200);
        const int u = isg ? tt : tt - 3200;
        const int m0 = isg ? (u >> 3) * 64 : (u >> 2) * 64;
        const int n0 = isg ? (u & 7) * 64 : (u & 3) * 64;
        const int NI = isg ? 4 : 8;

#define LOAD_PRE(k0, s) do {                                                    \
        int aoff = (s) * STW, boff = aoff + 64 * PIT;                           \
        _Pragma("unroll")                                                       \
        for (int jj = 0; jj < 4; jj++) {                                        \
            int cid = tid + jj * 256;                                           \
            int r = cid >> 4, q = cid & 15;                                     \
            int k = (k0) + q * 4;                                               \
            const unsigned* src = isg ? (g_dt + (size_t)(m0 + r) * Fn + k)      \
                                      : (g_gxm + (size_t)(m0 + r) * 512 + k);   \
            CP16(aoff + r * PIT + q * 4, src);                                  \
        }                                                                       \
        _Pragma("unroll")                                                       \
        for (int jj = 0; jj < 4; jj++) {                                        \
            int cid = tid + jj * 256;                                           \
            int r = cid >> 4, q = cid & 15;                                     \
            int k = (k0) + q * 4;                                               \
            const unsigned* src = isg ? (g_Wtdh + (size_t)(n0 + r) * Fn + k)    \
                                      : (g_Wcomb + (size_t)(n0 + r) * 512 + k); \
            CP16(boff + r * PIT + q * 4, src);                                  \
        }                                                                       \
    } while (0)

        LOAD_PRE(0, 0); CMT;
        LOAD_PRE(64, 1); CMT;
        LOAD_PRE(128, 2); CMT;
        for (int i = 0; i < NI; i++) {
            WAIT2;                         // own groups: stage i%4 complete
            __syncthreads();               // ALL threads' stage i%4 complete
            if (i + 3 < NI) LOAD_PRE((i + 3) * 64, (i + 3) & 3);
            CMT;
            int s = i & 3;
            mma64(SHu + s * STW, SHu + s * STW + 64 * PIT, acc, wm4, wn4, gid, tg);
        }
        __syncthreads();
#pragma unroll
        for (int nf = 0; nf < 4; nf++) {
#pragma unroll
            for (int e = 0; e < 4; e++) {
                int bt = m0 + wm4 * 16 + gid + ((e >> 1) << 3);
                int n = n0 + wn4 * 32 + nf * 8 + 2 * tg + (e & 1);
                float v = acc[nf][e];
                if (isg)
                    g_gamma_h[(size_t)bt * Hn + n] = expf(-fmaxf(v + b_td_h[n], 0.f));
                else
                    g_alpha[(size_t)bt * Fn + n] = sigmoidf_(v + b_comb[n]);
            }
        }
    }
    gsync(sense);

    // =================== sequential recurrence (dataflow-synced, 4 groups) ===================
    for (int t = 0; t < Tn; t++) {
        const int par = t & 1, nxt = (t + 1) & 1;

        // ===== P_a: x_h = h_dec @ W_hist^T  (group rows 64, N=256, K=512) =====
        if (cg < 16) {
            const int mh = cg >> 3;                 // 32-row half within group
            const int m0a = b0 + mh * 32;
            const int n0 = (cg & 7) * 32;
            wait_ge(&g_cnt_h[g], 32u * (unsigned)t);
            float acc[4] = {0.f, 0.f, 0.f, 0.f};
#define LOAD_PA(k0, s) do {                                                     \
            int aoff = (s) * STW, boff = aoff + 32 * PIT;                       \
            _Pragma("unroll")                                                   \
            for (int jj = 0; jj < 2; jj++) {                                    \
                int cid = tid + jj * 256;                                       \
                int r = cid >> 4, q = cid & 15;                                 \
                int k = (k0) + q * 4;                                           \
                CP16(aoff + r * PIT + q * 4, g_h[par] + (m0a + r) * Hn + k);    \
                CP16(boff + r * PIT + q * 4, g_Whist + (n0 + r) * Hn + k);      \
            }                                                                   \
        } while (0)
            LOAD_PA(0, 0); CMT;
            LOAD_PA(64, 1); CMT;
            LOAD_PA(128, 2); CMT;
            for (int i = 0; i < 8; i++) {
                WAIT2;
                __syncthreads();
                if (i + 3 < 8) LOAD_PA((i + 3) * 64, (i + 3) & 3);
                CMT;
                int s = i & 3;
                mma32(SHu + s * STW, SHu + s * STW + 32 * PIT, acc, wm2, wn2, gid, tg);
            }
            float ls = 0.0f;
#pragma unroll
            for (int e = 0; e < 4; e++) {
                int b = m0a + wm2 * 16 + gid + ((e >> 1) << 3);
                int f = n0 + wn2 * 8 + 2 * tg + (e & 1);
                float xh = acc[e] + b_hist[f];
                g_xh[b * Fn + f] = xh;
                size_t vi = (size_t)(b * Tn + t) * Fn + f;
                float x = values[vi], m = masks[vi];
                ls += fabsf(xh - x) * m;
                g_xc[b * Fn + f] = f2tf(m * x + (1.0f - m) * xh);
            }
            ls = wredsum(ls);
            if (lane == 0) RED[wid] = ls;
            __syncthreads();
            if (tid == 0) {
                float s = 0.f;
#pragma unroll
                for (int w = 0; w < 8; w++) s += RED[w];
                g_l1[t * 64 + g * 16 + cg] = s;
            }
            arrive(&g_cnt_xh[g * 2 + mh]);
        }

        // ===== P_b: z_h = relu(x_c @ Wf^T) + fused epilogue =====
        if (cg < 16) {
            const int mh = cg >> 3;
            const int m0a = b0 + mh * 32;
            const int n0 = (cg & 7) * 32;
            wait_ge(&g_cnt_xh[g * 2 + mh], 8u * (unsigned)(t + 1));
            float acc[4] = {0.f, 0.f, 0.f, 0.f};
#define LOAD_PB(k0, s) do {                                                     \
            int aoff = (s) * STW, boff = aoff + 32 * PIT;                       \
            _Pragma("unroll")                                                   \
            for (int jj = 0; jj < 2; jj++) {                                    \
                int cid = tid + jj * 256;                                       \
                int r = cid >> 4, q = cid & 15;                                 \
                int k = (k0) + q * 4;                                           \
                CP16(aoff + r * PIT + q * 4, g_xc + (m0a + r) * Fn + k);        \
                CP16(boff + r * PIT + q * 4, g_Wfeat + (n0 + r) * Fn + k);      \
            }                                                                   \
        } while (0)
            LOAD_PB(0, 0); CMT;
            LOAD_PB(64, 1); CMT;
            LOAD_PB(128, 2); CMT;
            for (int i = 0; i < 4; i++) {
                WAIT2;
                __syncthreads();
                if (i + 3 < 4) LOAD_PB((i + 3) * 64, (i + 3) & 3);
                CMT;
                int s = i & 3;
                mma32(SHu + s * STW, SHu + s * STW + 32 * PIT, acc, wm2, wn2, gid, tg);
            }
            float l2s = 0.f, l3s = 0.f, dns = 0.f;
#pragma unroll
            for (int e = 0; e < 4; e++) {
                int b = m0a + wm2 * 16 + gid + ((e >> 1) << 3);
                int f = n0 + wn2 * 8 + 2 * tg + (e & 1);
                size_t bt = (size_t)(b * Tn + t);
                float z = fmaxf(acc[e] + b_feat[f], 0.0f);
                float al = g_alpha[bt * Fn + f];
                float xh = g_xh[b * Fn + f];
                float ch = al * z + (1.0f - al) * xh;
                size_t vi = bt * Fn + f;
                float x = values[vi], m = masks[vi];
                float cc = m * x + (1.0f - m) * ch;
                out[vi] = cc;
                g_ccb[b * Fn + f] = f2tf(cc);
                l2s += fabsf(z - x) * m;
                l3s += fabsf(ch - x) * m;
                dns += m;
            }
            l2s = wredsum(l2s);
            l3s = wredsum(l3s);
            dns = wredsum(dns);
            if (lane == 0) { RED[wid] = l2s; RED[8 + wid] = l3s; RED[16 + wid] = dns; }
            __syncthreads();
            if (tid == 0) {
                float s2 = 0.f, s3 = 0.f, sd = 0.f;
#pragma unroll
                for (int w = 0; w < 8; w++) { s2 += RED[w]; s3 += RED[8 + w]; sd += RED[16 + w]; }
                int slot = t * 64 + g * 16 + cg;
                g_l2[slot] = s2; g_l3[slot] = s3; g_den[slot] = sd;
            }
            arrive(&g_cnt_cc[g]);
        }

        // ===== P_c: gates (64 x 64-virt x 1024) + fused LSTM =====
        {
            const int m0 = b0;
            const int w0 = cg * 64;
            const int j0 = cg * 16;
            wait_ge(&g_cnt_cc[g], 16u * (unsigned)(t + 1));
            float acc[4][4];
#pragma unroll
            for (int nf = 0; nf < 4; nf++)
#pragma unroll
                for (int e = 0; e < 4; e++) acc[nf][e] = 0.0f;

#define LOAD_PC(k0, s) do {                                                     \
            int aoff = (s) * STW, boff = aoff + 64 * PIT;                       \
            _Pragma("unroll")                                                   \
            for (int jj = 0; jj < 4; jj++) {                                    \
                int cid = tid + jj * 256;                                       \
                int r = cid >> 4, q = cid & 15;                                 \
                int k = (k0) + q * 4;                                           \
                int b = m0 + r;                                                 \
                const unsigned* src;                                            \
                if (k < 256)      src = g_ccb + b * Fn + k;                     \
                else if (k < 512) src = g_gxm + ((size_t)b * Tn + t) * 512 + k; \
                else              src = g_h[par] + b * Hn + (k - 512);          \
                CP16(aoff + r * PIT + q * 4, src);                              \
            }                                                                   \
            _Pragma("unroll")                                                   \
            for (int jj = 0; jj < 4; jj++) {                                    \
                int cid = tid + jj * 256;                                       \
                int r = cid >> 4, q = cid & 15;                                 \
                int k = (k0) + q * 4;                                           \
                CP16(boff + r * PIT + q * 4, g_Wg + (size_t)(w0 + r) * 1024 + k); \
            }                                                                   \
        } while (0)
            LOAD_PC(0, 0); CMT;
            LOAD_PC(64, 1); CMT;
            LOAD_PC(128, 2); CMT;
            for (int i = 0; i < 16; i++) {
                WAIT2;
                __syncthreads();
                if (i + 3 < 16) LOAD_PC((i + 3) * 64, (i + 3) & 3);
                CMT;
                int s = i & 3;
                mma64(SHu + s * STW, SHu + s * STW + 64 * PIT, acc, wm4, wn4, gid, tg);
            }
            __syncthreads();
            float* EP = (float*)SHu;
#pragma unroll
            for (int nf = 0; nf < 4; nf++)
#pragma unroll
                for (int e = 0; e < 4; e++) {
                    int r = wm4 * 16 + gid + ((e >> 1) << 3);
                    int cL = wn4 * 32 + nf * 8 + 2 * tg + (e & 1);
                    EP[r * PIT + cL] = acc[nf][e];
                }
            __syncthreads();
#pragma unroll
            for (int q = 0; q < 4; q++) {
                int idx = tid + q * 256;
                int r = idx >> 4, jl = idx & 15;
                int b = m0 + r;
                int j = j0 + jl;
                float ia = EP[r * PIT + jl * 4 + 0] + g_bg[j * 4 + 0];
                float fa = EP[r * PIT + jl * 4 + 1] + g_bg[j * 4 + 1];
                float ga = EP[r * PIT + jl * 4 + 2] + g_bg[j * 4 + 2];
                float oa = EP[r * PIT + jl * 4 + 3] + g_bg[j * 4 + 3];
                int ci = b * Hn + j;
                float cn = sigmoidf_(fa) * g_cst[ci] + sigmoidf_(ia) * tanhf(ga);
                float hn = sigmoidf_(oa) * tanhf(cn);
                g_cst[ci] = cn;
                if (t + 1 < Tn)
                    g_h[nxt][ci] = f2tf(hn * g_gamma_h[((size_t)b * Tn + t + 1) * Hn + j]);
                else
                    out[(size_t)Bn * Tn * Fn + ci] = hn;
            }
            arrive(&g_cnt_h[g]);
        }
    }

    gsync(sense);

    // =================== final deterministic loss reduction + counter reset ===================
    if (cta == 0) {
        float v = 0.0f;
        if (tid < Tn) {
            float den = 1e-9f, n1 = 0.f, n2 = 0.f, n3 = 0.f;
            for (int c2 = 0; c2 < 64; c2++) {
                den += g_den[tid * 64 + c2];
                n1 += g_l1[tid * 64 + c2];
                n2 += g_l2[tid * 64 + c2];
                n3 += g_l3[tid * 64 + c2];
            }
            v = (n1 + n2 + n3) / den;
        }
        __syncthreads();
        RED[tid] = v;
        __syncthreads();
#pragma unroll
        for (int s = 128; s > 0; s >>= 1) {
            if (tid < s) RED[tid] += RED[tid + s];
            __syncthreads();
        }
        if (tid == 0) {
            out[(size_t)Bn * Tn * Fn + Bn * Hn] = RED[0] / (3.0f * Tn);
            // reset dataflow counters for the next (graph-replayed) launch
#pragma unroll
            for (int i = 0; i < 4; i++) { g_cnt_h[i] = 0u; g_cnt_cc[i] = 0u; }
#pragma unroll
            for (int i = 0; i < 8; i++) g_cnt_xh[i] = 0u;
            __threadfence();
        }
    }
}

extern "C" void kernel_launch(void* const* d_in, const int* in_sizes, int n_in,
                              void* d_out, int out_size) {
    (void)in_sizes; (void)n_in; (void)out_size;
    static int configured = 0;
    if (!configured) {
        cudaFuncSetAttribute(rits_kernel, cudaFuncAttributeMaxDynamicSharedMemorySize,
                             SMEM_BYTES);
        configured = 1;
    }
    rits_kernel<<<NB, NT, SMEM_BYTES>>>(
        (const float*)d_in[0],  (const float*)d_in[1],  (const float*)d_in[2],
        (const float*)d_in[3],  (const float*)d_in[4],  (const float*)d_in[5],
        (const float*)d_in[6],  (const float*)d_in[7],  (const float*)d_in[8],
        (const float*)d_in[9],  (const float*)d_in[10], (const float*)d_in[11],
        (const float*)d_in[12], (const float*)d_in[13], (const float*)d_in[14],
        (const float*)d_in[15], (const float*)d_in[16],
        (float*)d_out);
}

// round 7
// speedup vs baseline: 4.6117x; 1.1179x over previous
#include <cuda_runtime.h>
#include <math.h>

#define Bn 256
#define Tn 100
#define Fn 256
#define Hn 512
#define NB 128
#define NT 256
#define BT (Bn * Tn)
#define STW 8192                   // stage words: A 4096 + B 4096
#define NSTG 4
#define EPIT 68
#define SMEM_WORDS (NSTG * STW + 256)
#define SMEM_BYTES (SMEM_WORDS * 4)
#define BTF ((size_t)Bn * Tn * Fn)

// ---------------- global scratch (allocation-free rule) ----------------
// quad (fragment-order) operand tensors
__device__ unsigned g_dtq[(size_t)400 * 4 * 4096];   // deltas, bt-tiles
__device__ unsigned g_gxmq[(size_t)400 * 8 * 4096];  // [gamma_x | mask], bt-tiles
__device__ unsigned g_mq[(size_t)4 * Tn * 4 * 4096]; // masks, (group,t)-tiles for P_c
__device__ unsigned g_Wtdhq[8 * 4 * 4096];
__device__ unsigned g_Wcombq[4 * 8 * 4096];
__device__ unsigned g_Whistq[8 * 8 * 2048];
__device__ unsigned g_Wfeatq[8 * 4 * 2048];
__device__ unsigned g_Wgq[32 * 16 * 4096];           // gates W, rows j*4+gate
__device__ unsigned g_hq[2 * 4 * 8 * 4096];          // h_dec quads (double buffer)
__device__ unsigned g_xcq[4 * 4 * 4096];
__device__ unsigned g_ccq[4 * 4 * 4096];
// row-major scalars
__device__ float g_gamma_h[(size_t)BT * Hn];
__device__ float g_alpha[(size_t)BT * Fn];
__device__ float g_bg[4 * Hn];
__device__ float g_cst[Bn * Hn];
__device__ float g_l1[Tn * 32], g_l2[Tn * 32], g_l3[Tn * 32], g_den[Tn * 32];
__device__ unsigned g_cnt, g_sense;
__device__ unsigned g_cnt_h[4], g_cnt_xh[4], g_cnt_cc[4];

__device__ __forceinline__ float sigmoidf_(float x) { return 1.0f / (1.0f + expf(-x)); }

__device__ __forceinline__ unsigned f2tf(float f) {
    unsigned u;
    asm("cvt.rna.tf32.f32 %0, %1;" : "=r"(u) : "f"(f));
    return u;
}

// quad layouts: word offset of element within a tile.
// A tiles: 64 rows x 64 k. Quad = {a0,a1,a2,a3} of one m16k8 fragment.
__device__ __forceinline__ int o_A(int r, int k) {
    return ((r >> 4) * 8 + (k >> 3)) * 128 + ((r & 7) * 4 + (k & 3)) * 4 +
           ((k & 4) >> 1) + ((r & 8) >> 3);
}
// B tiles: (32|64) n-rows x 64 k. Quad = {b0,b1} of two adjacent n-fragments.
__device__ __forceinline__ int o_B(int n, int k) {
    return ((n >> 4) * 8 + (k >> 3)) * 128 + ((n & 7) * 4 + (k & 3)) * 4 +
           ((n >> 3) & 1) * 2 + ((k >> 2) & 1);
}

#define MMA(d, A0, A1, A2, A3, B0, B1)                                          \
    asm volatile("mma.sync.aligned.m16n8k8.row.col.f32.tf32.tf32.f32 "          \
                 "{%0,%1,%2,%3},{%4,%5,%6,%7},{%8,%9},{%0,%1,%2,%3};"           \
                 : "+f"(d[0]), "+f"(d[1]), "+f"(d[2]), "+f"(d[3])               \
                 : "r"(A0), "r"(A1), "r"(A2), "r"(A3), "r"(B0), "r"(B1))

#define CPA(boff, p)                                                            \
    asm volatile("cp.async.cg.shared.global [%0], [%1], 16;"                    \
                 :: "r"(sbase + (unsigned)(boff)), "l"(p) : "memory")
#define CMT   asm volatile("cp.async.commit_group;" ::: "memory")
#define WAIT2 asm volatile("cp.async.wait_group 2;" ::: "memory")

// 64x64 stage (A 4096 + B 4096 words), linear copy
#define LOADQ64(pA, pB, s) do {                                                 \
    unsigned _off = (unsigned)((s) * STW * 4);                                  \
    _Pragma("unroll")                                                           \
    for (int _j = 0; _j < 4; _j++) { int _c = tid + _j * 256;                   \
        CPA(_off + (unsigned)_c * 16u, (pA) + _c * 4);                          \
        CPA(_off + 16384u + (unsigned)_c * 16u, (pB) + _c * 4); }               \
} while (0)
// 64x32 stage (A 4096 + B 2048 words)
#define LOADQ32(pA, pB, s) do {                                                 \
    unsigned _off = (unsigned)((s) * STW * 4);                                  \
    _Pragma("unroll")                                                           \
    for (int _j = 0; _j < 4; _j++) { int _c = tid + _j * 256;                   \
        CPA(_off + (unsigned)_c * 16u, (pA) + _c * 4); }                        \
    _Pragma("unroll")                                                           \
    for (int _j = 0; _j < 2; _j++) { int _c = tid + _j * 256;                   \
        CPA(_off + 16384u + (unsigned)_c * 16u, (pB) + _c * 4); }               \
} while (0)

// ---------------- sync primitives (proven in round 6) ----------------
__device__ __forceinline__ void gsync(unsigned& sense) {
    __threadfence();
    __syncthreads();
    unsigned target = sense ^ 1u;
    if (threadIdx.x == 0) {
        unsigned old = atomicAdd(&g_cnt, 1u);
        if (old == NB - 1) {
            g_cnt = 0;
            __threadfence();
            atomicExch(&g_sense, target);
        } else {
            while (atomicAdd(&g_sense, 0u) != target) { __nanosleep(128); }
        }
        __threadfence();
    }
    sense = target;
    __syncthreads();
}
__device__ __forceinline__ void wait_ge(unsigned* cnt, unsigned target) {
    if (threadIdx.x == 0) {
        while (atomicAdd(cnt, 0u) < target) { __nanosleep(64); }
        __threadfence();
    }
    __syncthreads();
}
__device__ __forceinline__ void arrive(unsigned* cnt) {
    __threadfence();
    __syncthreads();
    if (threadIdx.x == 0) atomicAdd(cnt, 1u);
}
__device__ __forceinline__ float wredsum(float v) {
#pragma unroll
    for (int o = 16; o; o >>= 1) v += __shfl_xor_sync(0xffffffffu, v, o);
    return v;
}

// ---------------- quad MMA bodies ----------------
// 64x64 tile: warps 4(M)x2(N), warp tile 16x32
__device__ __forceinline__ void mma64q(const unsigned* As, const unsigned* Bs,
                                       float acc[4][4], int wm, int wn, int lane) {
#pragma unroll
    for (int ks = 0; ks < 8; ks++) {
        uint4 a = *(const uint4*)&As[((wm * 8 + ks) * 32 + lane) * 4];
        uint4 b0 = *(const uint4*)&Bs[(((wn * 2 + 0) * 8 + ks) * 32 + lane) * 4];
        uint4 b1 = *(const uint4*)&Bs[(((wn * 2 + 1) * 8 + ks) * 32 + lane) * 4];
        MMA(acc[0], a.x, a.y, a.z, a.w, b0.x, b0.y);
        MMA(acc[1], a.x, a.y, a.z, a.w, b0.z, b0.w);
        MMA(acc[2], a.x, a.y, a.z, a.w, b1.x, b1.y);
        MMA(acc[3], a.x, a.y, a.z, a.w, b1.z, b1.w);
    }
}
// 64x32 tile: warps 4(M)x2(N), warp tile 16x16
__device__ __forceinline__ void mma32q(const unsigned* As, const unsigned* Bs,
                                       float acc[2][4], int wm, int wn, int lane) {
#pragma unroll
    for (int ks = 0; ks < 8; ks++) {
        uint4 a = *(const uint4*)&As[((wm * 8 + ks) * 32 + lane) * 4];
        uint4 b = *(const uint4*)&Bs[((wn * 8 + ks) * 32 + lane) * 4];
        MMA(acc[0], a.x, a.y, a.z, a.w, b.x, b.y);
        MMA(acc[1], a.x, a.y, a.z, a.w, b.z, b.w);
    }
}

__device__ __forceinline__ const unsigned* pcA(int g, int t, int par, int kc) {
    if (kc < 4)  return g_ccq + ((size_t)g * 4 + kc) * 4096;
    if (kc < 8)  return g_mq + (((size_t)g * Tn + t) * 4 + (kc - 4)) * 4096;
    return g_hq + (((size_t)par * 4 + g) * 8 + (kc - 8)) * 4096;
}

__global__ void __launch_bounds__(NT, 1) rits_kernel(
    const float* __restrict__ values, const float* __restrict__ masks,
    const float* __restrict__ deltas,
    const float* __restrict__ W_td_h, const float* __restrict__ b_td_h,
    const float* __restrict__ W_td_x, const float* __restrict__ b_td_x,
    const float* __restrict__ W_hist, const float* __restrict__ b_hist,
    const float* __restrict__ W_feat, const float* __restrict__ b_feat,
    const float* __restrict__ W_comb, const float* __restrict__ b_comb,
    const float* __restrict__ W_ih, const float* __restrict__ W_hh,
    const float* __restrict__ b_ih, const float* __restrict__ b_hh,
    float* __restrict__ out)
{
    extern __shared__ unsigned SHu[];
    float* RED = (float*)(SHu + NSTG * STW);
    unsigned sbase = (unsigned)__cvta_generic_to_shared(SHu);

    const int tid = threadIdx.x;
    const int cta = blockIdx.x;
    const int wid = tid >> 5;
    const int lane = tid & 31;
    const int gid = lane >> 2;
    const int tg = lane & 3;
    const int wm = wid & 3, wn = wid >> 2;

    const int g = cta >> 5;
    const int cg = cta & 31;
    const int b0 = g * 64;

    unsigned sense = *((volatile unsigned*)&g_sense);

    // =================== init: state + tf32 quad pre-conversion ===================
    for (int i = cta * NT + tid; i < Bn * Hn; i += NB * NT) g_cst[i] = 0.0f;
    for (int i = cta * NT + tid; i < 2 * 4 * 8 * 4096; i += NB * NT) g_hq[i] = 0u;

    // deltas -> g_dtq; gamma_x|mask -> g_gxmq; mask -> g_mq
    for (int i4 = cta * NT + tid; i4 < BT * Fn / 4; i4 += NB * NT) {
        int bt = i4 >> 6;
        int f0 = (i4 & 63) * 4;
        float4 d = ((const float4*)deltas)[i4];
        float4 mk = ((const float4*)masks)[i4];
        int u = bt >> 6, r = bt & 63;
        int b = bt / Tn;
        int tt2 = bt - b * Tn;
        int g2 = b >> 6, r2 = b & 63;
        float dv[4] = {d.x, d.y, d.z, d.w};
        float mv[4] = {mk.x, mk.y, mk.z, mk.w};
#pragma unroll
        for (int q = 0; q < 4; q++) {
            int f = f0 + q;
            int kc = f >> 6, k = f & 63;
            int oa = o_A(r, k);
            float gx = expf(-fmaxf(fmaf(dv[q], W_td_x[f * Fn + f], b_td_x[f]), 0.f));
            unsigned mu = f2tf(mv[q]);
            g_dtq[((size_t)u * 4 + kc) * 4096 + oa] = f2tf(dv[q]);
            g_gxmq[((size_t)u * 8 + kc) * 4096 + oa] = f2tf(gx);
            g_gxmq[((size_t)u * 8 + 4 + kc) * 4096 + oa] = mu;
            g_mq[(((size_t)g2 * Tn + tt2) * 4 + kc) * 4096 + o_A(r2, k)] = mu;
        }
    }
    // weights
    for (int i = cta * NT + tid; i < 512 * 256; i += NB * NT) {
        int n = i >> 8, k = i & 255;
        g_Wtdhq[((n >> 6) * 4 + (k >> 6)) * 4096 + o_B(n & 63, k & 63)] = f2tf(W_td_h[i]);
    }
    for (int i = cta * NT + tid; i < 256 * 512; i += NB * NT) {
        int n = i >> 9, k = i & 511;
        g_Wcombq[((n >> 6) * 8 + (k >> 6)) * 4096 + o_B(n & 63, k & 63)] = f2tf(W_comb[i]);
        g_Whistq[((n >> 5) * 8 + (k >> 6)) * 2048 + o_B(n & 31, k & 63)] = f2tf(W_hist[i]);
    }
    for (int i = cta * NT + tid; i < 256 * 256; i += NB * NT) {
        int n = i >> 8, k = i & 255;
        float w = (n == k) ? 0.0f : W_feat[i];
        g_Wfeatq[((n >> 5) * 4 + (k >> 6)) * 2048 + o_B(n & 31, k & 63)] = f2tf(w);
    }
    for (int i = cta * NT + tid; i < 2048 * 1024; i += NB * NT) {
        int np = i >> 10, k = i & 1023;
        int j = np >> 2, gate = np & 3;
        float w = (k < 512) ? W_ih[(size_t)(gate * Hn + j) * 512 + k]
                            : W_hh[(size_t)(gate * Hn + j) * 512 + (k - 512)];
        g_Wgq[((np >> 6) * 16 + (k >> 6)) * 4096 + o_B(np & 63, k & 63)] = f2tf(w);
    }
    for (int i = cta * NT + tid; i < 4 * Hn; i += NB * NT) {
        int j = i >> 2, gate = i & 3;
        g_bg[i] = b_ih[gate * Hn + j] + b_hh[gate * Hn + j];
    }
    gsync(sense);

    // =================== precompute gamma_h (3200 tiles) + alpha (1600) ===================
    for (int tt = cta; tt < 4800; tt += NB) {
        float acc[4][4];
#pragma unroll
        for (int nf = 0; nf < 4; nf++)
#pragma unroll
            for (int e = 0; e < 4; e++) acc[nf][e] = 0.0f;

        const bool isg = (tt < 3200);
        const int u = isg ? tt : tt - 3200;
        const int ut = isg ? (u >> 3) : (u >> 2);
        const int nt = isg ? (u & 7) : (u & 3);
        const int m0 = ut * 64, n0 = nt * 64;
        const int NI = isg ? 4 : 8;
        const unsigned* Asrc = isg ? (g_dtq + (size_t)ut * 4 * 4096)
                                   : (g_gxmq + (size_t)ut * 8 * 4096);
        const unsigned* Bsrc = isg ? (g_Wtdhq + (size_t)nt * 4 * 4096)
                                   : (g_Wcombq + (size_t)nt * 8 * 4096);

        LOADQ64(Asrc, Bsrc, 0); CMT;
        LOADQ64(Asrc + 4096, Bsrc + 4096, 1); CMT;
        LOADQ64(Asrc + 8192, Bsrc + 8192, 2); CMT;
        for (int i = 0; i < NI; i++) {
            WAIT2;
            __syncthreads();
            if (i + 3 < NI)
                LOADQ64(Asrc + (size_t)(i + 3) * 4096, Bsrc + (size_t)(i + 3) * 4096, (i + 3) & 3);
            CMT;
            int s = i & 3;
            mma64q(SHu + s * STW, SHu + s * STW + 4096, acc, wm, wn, lane);
        }
        __syncthreads();
#pragma unroll
        for (int nf = 0; nf < 4; nf++) {
#pragma unroll
            for (int e = 0; e < 4; e++) {
                int bt = m0 + wm * 16 + gid + ((e >> 1) << 3);
                int n = n0 + wn * 32 + nf * 8 + 2 * tg + (e & 1);
                float v = acc[nf][e];
                if (isg)
                    g_gamma_h[(size_t)bt * Hn + n] = expf(-fmaxf(v + b_td_h[n], 0.f));
                else
                    g_alpha[(size_t)bt * Fn + n] = sigmoidf_(v + b_comb[n]);
            }
        }
    }
    gsync(sense);

    // =================== sequential recurrence (dataflow-synced, 4 groups) ===================
    for (int t = 0; t < Tn; t++) {
        const int par = t & 1, nxt = (t + 1) & 1;
        float xh_r[2][4], x_r[2][4], m_r[2][4];

        // ===== P_a: x_h = h_dec @ W_hist^T  (tile 64x32, K=512), CTAs cg<8 =====
        if (cg < 8) {
            const int n0 = cg * 32;
            wait_ge(&g_cnt_h[g], 32u * (unsigned)t);
            const unsigned* Ah = g_hq + (((size_t)par * 4 + g) * 8) * 4096;
            const unsigned* Bw = g_Whistq + (size_t)cg * 8 * 2048;
            float acc[2][4];
#pragma unroll
            for (int nf = 0; nf < 2; nf++)
#pragma unroll
                for (int e = 0; e < 4; e++) acc[nf][e] = 0.0f;
            LOADQ32(Ah, Bw, 0); CMT;
            LOADQ32(Ah + 4096, Bw + 2048, 1); CMT;
            LOADQ32(Ah + 8192, Bw + 4096, 2); CMT;
            for (int i = 0; i < 8; i++) {
                WAIT2;
                __syncthreads();
                if (i + 3 < 8)
                    LOADQ32(Ah + (size_t)(i + 3) * 4096, Bw + (size_t)(i + 3) * 2048, (i + 3) & 3);
                CMT;
                int s = i & 3;
                mma32q(SHu + s * STW, SHu + s * STW + 4096, acc, wm, wn, lane);
            }
            float ls = 0.0f;
#pragma unroll
            for (int nf = 0; nf < 2; nf++) {
#pragma unroll
                for (int e = 0; e < 4; e++) {
                    int r = wm * 16 + gid + ((e >> 1) << 3);
                    int b = b0 + r;
                    int f = n0 + wn * 16 + nf * 8 + 2 * tg + (e & 1);
                    float xh = acc[nf][e] + b_hist[f];
                    size_t vi = ((size_t)b * Tn + t) * Fn + f;
                    float x = values[vi], m = masks[vi];
                    xh_r[nf][e] = xh; x_r[nf][e] = x; m_r[nf][e] = m;
                    ls += fabsf(xh - x) * m;
                    g_xcq[((size_t)g * 4 + (f >> 6)) * 4096 + o_A(r, f & 63)] =
                        f2tf(m * x + (1.0f - m) * xh);
                }
            }
            ls = wredsum(ls);
            if (lane == 0) RED[wid] = ls;
            __syncthreads();
            if (tid == 0) {
                float s = 0.f;
#pragma unroll
                for (int w = 0; w < 8; w++) s += RED[w];
                g_l1[t * 32 + g * 8 + cg] = s;
            }
            arrive(&g_cnt_xh[g]);
        }

        // ===== P_b: z_h = relu(x_c @ Wf^T) (tile 64x32, K=256) + epilogue =====
        if (cg < 8) {
            const int n0 = cg * 32;
            wait_ge(&g_cnt_xh[g], 8u * (unsigned)(t + 1));
            const unsigned* Ax = g_xcq + (size_t)g * 4 * 4096;
            const unsigned* Bf = g_Wfeatq + (size_t)cg * 4 * 2048;
            float acc[2][4];
#pragma unroll
            for (int nf = 0; nf < 2; nf++)
#pragma unroll
                for (int e = 0; e < 4; e++) acc[nf][e] = 0.0f;
            LOADQ32(Ax, Bf, 0); CMT;
            LOADQ32(Ax + 4096, Bf + 2048, 1); CMT;
            LOADQ32(Ax + 8192, Bf + 4096, 2); CMT;
            for (int i = 0; i < 4; i++) {
                WAIT2;
                __syncthreads();
                if (i + 3 < 4)
                    LOADQ32(Ax + (size_t)(i + 3) * 4096, Bf + (size_t)(i + 3) * 2048, (i + 3) & 3);
                CMT;
                int s = i & 3;
                mma32q(SHu + s * STW, SHu + s * STW + 4096, acc, wm, wn, lane);
            }
            float l2s = 0.f, l3s = 0.f, dns = 0.f;
#pragma unroll
            for (int nf = 0; nf < 2; nf++) {
#pragma unroll
                for (int e = 0; e < 4; e++) {
                    int r = wm * 16 + gid + ((e >> 1) << 3);
                    int b = b0 + r;
                    int f = n0 + wn * 16 + nf * 8 + 2 * tg + (e & 1);
                    size_t vi = ((size_t)b * Tn + t) * Fn + f;
                    float z = fmaxf(acc[nf][e] + b_feat[f], 0.0f);
                    float al = g_alpha[vi];
                    float x = x_r[nf][e], m = m_r[nf][e];
                    float ch = al * z + (1.0f - al) * xh_r[nf][e];
                    float cc = m * x + (1.0f - m) * ch;
                    out[vi] = cc;
                    g_ccq[((size_t)g * 4 + (f >> 6)) * 4096 + o_A(r, f & 63)] = f2tf(cc);
                    l2s += fabsf(z - x) * m;
                    l3s += fabsf(ch - x) * m;
                    dns += m;
                }
            }
            l2s = wredsum(l2s); l3s = wredsum(l3s); dns = wredsum(dns);
            if (lane == 0) { RED[wid] = l2s; RED[8 + wid] = l3s; RED[16 + wid] = dns; }
            __syncthreads();
            if (tid == 0) {
                float s2 = 0.f, s3 = 0.f, sd = 0.f;
#pragma unroll
                for (int w = 0; w < 8; w++) { s2 += RED[w]; s3 += RED[8 + w]; sd += RED[16 + w]; }
                int slot = t * 32 + g * 8 + cg;
                g_l2[slot] = s2; g_l3[slot] = s3; g_den[slot] = sd;
            }
            arrive(&g_cnt_cc[g]);
        }

        // ===== P_c: gates (tile 64x64 virt, K=1024) + fused LSTM, all 32 CTAs =====
        {
            wait_ge(&g_cnt_cc[g], 8u * (unsigned)(t + 1));
            const unsigned* Bb = g_Wgq + (size_t)cg * 16 * 4096;
            float acc[4][4];
#pragma unroll
            for (int nf = 0; nf < 4; nf++)
#pragma unroll
                for (int e = 0; e < 4; e++) acc[nf][e] = 0.0f;
            LOADQ64(pcA(g, t, par, 0), Bb, 0); CMT;
            LOADQ64(pcA(g, t, par, 1), Bb + 4096, 1); CMT;
            LOADQ64(pcA(g, t, par, 2), Bb + 8192, 2); CMT;
            for (int i = 0; i < 16; i++) {
                WAIT2;
                __syncthreads();
                if (i + 3 < 16)
                    LOADQ64(pcA(g, t, par, i + 3), Bb + (size_t)(i + 3) * 4096, (i + 3) & 3);
                CMT;
                int s = i & 3;
                mma64q(SHu + s * STW, SHu + s * STW + 4096, acc, wm, wn, lane);
            }
            __syncthreads();
            float* EP = (float*)SHu;
#pragma unroll
            for (int nf = 0; nf < 4; nf++)
#pragma unroll
                for (int e = 0; e < 4; e++) {
                    int r = wm * 16 + gid + ((e >> 1) << 3);
                    int cL = wn * 32 + nf * 8 + 2 * tg + (e & 1);
                    EP[r * EPIT + cL] = acc[nf][e];
                }
            __syncthreads();
#pragma unroll
            for (int q = 0; q < 4; q++) {
                int idx = tid + q * 256;
                int r = idx >> 4, jl = idx & 15;
                int b = b0 + r;
                int j = cg * 16 + jl;
                float ia = EP[r * EPIT + jl * 4 + 0] + g_bg[j * 4 + 0];
                float fa = EP[r * EPIT + jl * 4 + 1] + g_bg[j * 4 + 1];
                float ga = EP[r * EPIT + jl * 4 + 2] + g_bg[j * 4 + 2];
                float oa = EP[r * EPIT + jl * 4 + 3] + g_bg[j * 4 + 3];
                int ci = b * Hn + j;
                float cn = sigmoidf_(fa) * g_cst[ci] + sigmoidf_(ia) * tanhf(ga);
                float hn = sigmoidf_(oa) * tanhf(cn);
                g_cst[ci] = cn;
                if (t + 1 < Tn) {
                    float hd = hn * g_gamma_h[((size_t)b * Tn + t + 1) * Hn + j];
                    g_hq[(((size_t)nxt * 4 + g) * 8 + (j >> 6)) * 4096 + o_A(r, j & 63)] = f2tf(hd);
                } else {
                    out[BTF + ci] = hn;
                }
            }
            arrive(&g_cnt_h[g]);
        }
    }

    gsync(sense);

    // =================== final deterministic loss reduction + counter reset ===================
    if (cta == 0) {
        float v = 0.0f;
        if (tid < Tn) {
            float den = 1e-9f, n1 = 0.f, n2 = 0.f, n3 = 0.f;
            for (int c2 = 0; c2 < 32; c2++) {
                den += g_den[tid * 32 + c2];
                n1 += g_l1[tid * 32 + c2];
                n2 += g_l2[tid * 32 + c2];
                n3 += g_l3[tid * 32 + c2];
            }
            v = (n1 + n2 + n3) / den;
        }
        __syncthreads();
        RED[tid] = v;
        __syncthreads();
#pragma unroll
        for (int s = 128; s > 0; s >>= 1) {
            if (tid < s) RED[tid] += RED[tid + s];
            __syncthreads();
        }
        if (tid == 0) {
            out[BTF + Bn * Hn] = RED[0] / (3.0f * Tn);
#pragma unroll
            for (int i = 0; i < 4; i++) { g_cnt_h[i] = 0u; g_cnt_xh[i] = 0u; g_cnt_cc[i] = 0u; }
            __threadfence();
        }
    }
}

extern "C" void kernel_launch(void* const* d_in, const int* in_sizes, int n_in,
                              void* d_out, int out_size) {
    (void)in_sizes; (void)n_in; (void)out_size;
    static int configured = 0;
    if (!configured) {
        cudaFuncSetAttribute(rits_kernel, cudaFuncAttributeMaxDynamicSharedMemorySize,
                             SMEM_BYTES);
        configured = 1;
    }
    rits_kernel<<<NB, NT, SMEM_BYTES>>>(
        (const float*)d_in[0],  (const float*)d_in[1],  (const float*)d_in[2],
        (const float*)d_in[3],  (const float*)d_in[4],  (const float*)d_in[5],
        (const float*)d_in[6],  (const float*)d_in[7],  (const float*)d_in[8],
        (const float*)d_in[9],  (const float*)d_in[10], (const float*)d_in[11],
        (const float*)d_in[12], (const float*)d_in[13], (const float*)d_in[14],
        (const float*)d_in[15], (const float*)d_in[16],
        (float*)d_out);
}